// round 1
// baseline (speedup 1.0000x reference)
#include <cuda_runtime.h>

// Problem constants
#define BB 2
#define SS 2048
#define DD 1024
#define HH 16
#define HD 64

// Intermediate Q/K/V buffers (device globals: no allocation allowed)
__device__ float g_Q[BB * SS * DD];
__device__ float g_K[BB * SS * DD];
__device__ float g_V[BB * SS * DD];

// ---------------- packed f32x2 helpers (FFMA2: 2x fp32 FMA throughput) ----------------
__device__ __forceinline__ unsigned long long pk2(float lo, float hi) {
    unsigned int l = __float_as_uint(lo), h = __float_as_uint(hi);
    unsigned long long r;
    asm("mov.b64 %0, {%1,%2};" : "=l"(r) : "r"(l), "r"(h));
    return r;
}
__device__ __forceinline__ void upk2(unsigned long long v, float& lo, float& hi) {
    unsigned int l, h;
    asm("mov.b64 {%0,%1}, %2;" : "=r"(l), "=r"(h) : "l"(v));
    lo = __uint_as_float(l);
    hi = __uint_as_float(h);
}
__device__ __forceinline__ unsigned long long ffma2(unsigned long long a, unsigned long long b,
                                                    unsigned long long c) {
    unsigned long long d;
    asm("fma.rn.f32x2 %0, %1, %2, %3;" : "=l"(d) : "l"(a), "l"(b), "l"(c));
    return d;
}
__device__ __forceinline__ unsigned long long fmul2(unsigned long long a, unsigned long long b) {
    unsigned long long d;
    asm("mul.rn.f32x2 %0, %1, %2;" : "=l"(d) : "l"(a), "l"(b));
    return d;
}

// ---------------- QKV projection GEMM ----------------
// C[m,n] = relu(sum_k X[m,k] * W[n,k] + bias[n])   (torch Linear: y = x @ W^T + b)
// M = 4096 (B*S), N = K = 1024. Tile 128x128x16, 256 threads, 8x8 per thread via f32x2.
__global__ void __launch_bounds__(256, 2) qkv_gemm(
    const float* __restrict__ Xq, const float* __restrict__ Xk, const float* __restrict__ Xv,
    const float* __restrict__ Wq, const float* __restrict__ Wk, const float* __restrict__ Wv,
    const float* __restrict__ bq, const float* __restrict__ bk, const float* __restrict__ bv) {
    const float* X;
    const float* W;
    const float* bias;
    float* out;
    if (blockIdx.z == 0)      { X = Xq; W = Wq; bias = bq; out = g_Q; }
    else if (blockIdx.z == 1) { X = Xk; W = Wk; bias = bk; out = g_K; }
    else                      { X = Xv; W = Wv; bias = bv; out = g_V; }

    __shared__ float Xs[16][132];  // [k][m], padded stride 132 (conflict-light, float4-aligned)
    __shared__ float Ws[16][132];  // [k][n]

    const int tid = threadIdx.x;
    const int bm = blockIdx.y * 128;
    const int bn = blockIdx.x * 128;
    const int tm = (tid >> 4) * 8;
    const int tn = (tid & 15) * 8;

    const int lrow = tid >> 2;        // 0..63 (two row batches: lrow, lrow+64)
    const int lk4 = (tid & 3) * 4;    // k offset within the 16-wide k-tile

    unsigned long long acc[8][4];
#pragma unroll
    for (int i = 0; i < 8; i++)
#pragma unroll
        for (int j = 0; j < 4; j++) acc[i][j] = 0ull;

    for (int k0 = 0; k0 < 1024; k0 += 16) {
        float4 xv0 = *(const float4*)&X[(bm + lrow) * 1024 + k0 + lk4];
        float4 xv1 = *(const float4*)&X[(bm + lrow + 64) * 1024 + k0 + lk4];
        float4 wv0 = *(const float4*)&W[(bn + lrow) * 1024 + k0 + lk4];
        float4 wv1 = *(const float4*)&W[(bn + lrow + 64) * 1024 + k0 + lk4];
        __syncthreads();  // previous tile's compute done reading smem
        Xs[lk4 + 0][lrow] = xv0.x; Xs[lk4 + 1][lrow] = xv0.y;
        Xs[lk4 + 2][lrow] = xv0.z; Xs[lk4 + 3][lrow] = xv0.w;
        Xs[lk4 + 0][lrow + 64] = xv1.x; Xs[lk4 + 1][lrow + 64] = xv1.y;
        Xs[lk4 + 2][lrow + 64] = xv1.z; Xs[lk4 + 3][lrow + 64] = xv1.w;
        Ws[lk4 + 0][lrow] = wv0.x; Ws[lk4 + 1][lrow] = wv0.y;
        Ws[lk4 + 2][lrow] = wv0.z; Ws[lk4 + 3][lrow] = wv0.w;
        Ws[lk4 + 0][lrow + 64] = wv1.x; Ws[lk4 + 1][lrow + 64] = wv1.y;
        Ws[lk4 + 2][lrow + 64] = wv1.z; Ws[lk4 + 3][lrow + 64] = wv1.w;
        __syncthreads();

#pragma unroll
        for (int k = 0; k < 16; k++) {
            float4 a0 = *(const float4*)&Xs[k][tm];
            float4 a1 = *(const float4*)&Xs[k][tm + 4];
            float4 b0 = *(const float4*)&Ws[k][tn];
            float4 b1 = *(const float4*)&Ws[k][tn + 4];
            unsigned long long bb[4] = {pk2(b0.x, b0.y), pk2(b0.z, b0.w),
                                        pk2(b1.x, b1.y), pk2(b1.z, b1.w)};
            float a[8] = {a0.x, a0.y, a0.z, a0.w, a1.x, a1.y, a1.z, a1.w};
#pragma unroll
            for (int i = 0; i < 8; i++) {
                unsigned long long aa = pk2(a[i], a[i]);
#pragma unroll
                for (int j = 0; j < 4; j++) acc[i][j] = ffma2(aa, bb[j], acc[i][j]);
            }
        }
    }

    // epilogue: bias + relu + store
    float bias8[8];
#pragma unroll
    for (int jj = 0; jj < 8; jj++) bias8[jj] = bias[bn + tn + jj];
#pragma unroll
    for (int i = 0; i < 8; i++) {
        int m = bm + tm + i;
        float o[8];
#pragma unroll
        for (int j = 0; j < 4; j++) upk2(acc[i][j], o[2 * j], o[2 * j + 1]);
#pragma unroll
        for (int jj = 0; jj < 8; jj++) {
            float v = o[jj] + bias8[jj];
            o[jj] = v > 0.0f ? v : 0.0f;
        }
        *(float4*)&out[m * 1024 + bn + tn] = make_float4(o[0], o[1], o[2], o[3]);
        *(float4*)&out[m * 1024 + bn + tn + 4] = make_float4(o[4], o[5], o[6], o[7]);
    }
}

// ---------------- flash attention + scrambled-reshape epilogue + residual ----------------
// One block = (batch b, head h, 64-query tile). Online softmax over 32 key tiles of 64.
// Masked query rows (attention_mask==0): logits forced to 0 -> uniform softmax == reference.
#define SPAD 68  // row stride for 64-wide smem tiles (float4-aligned, conflict-light)
#define ATTN_SMEM (4 * 64 * SPAD * 4)

__global__ void __launch_bounds__(256) attn_kernel(const int* __restrict__ amask,
                                                   const float* __restrict__ queries,
                                                   float* __restrict__ out) {
    extern __shared__ float sm[];
    float* Qt = sm;                   // [d][q]  transposed, stride SPAD
    float* Kt = Qt + 64 * SPAD;       // [d][kk] transposed
    float* Vs = Kt + 64 * SPAD;       // [kk][d] natural
    float* Ss = Vs + 64 * SPAD;       // [q][kk] scores -> probs -> final O
    __shared__ float rowm[64], rowl[64], rowc[64];
    __shared__ int mrow[64];

    const int tid = threadIdx.x;
    const int b = blockIdx.z;
    const int h = blockIdx.y;
    const int q0 = blockIdx.x * 64;

    const int tq = (tid >> 4) * 4;  // 4 query rows per thread
    const int tk = (tid & 15) * 4;  // 4 key cols (also 4 d cols in PV phase)

    const int lr = tid >> 2;  // tile row for loads (0..63)

    // load Q tile transposed (once)
#pragma unroll
    for (int t = 0; t < 4; t++) {
        int d4 = (tid & 3) * 4 + t * 16;
        float4 qv = *(const float4*)&g_Q[(b * 2048 + q0 + lr) * 1024 + h * 64 + d4];
        Qt[(d4 + 0) * SPAD + lr] = qv.x;
        Qt[(d4 + 1) * SPAD + lr] = qv.y;
        Qt[(d4 + 2) * SPAD + lr] = qv.z;
        Qt[(d4 + 3) * SPAD + lr] = qv.w;
    }
    if (tid < 64) {
        rowm[tid] = -1e30f;
        rowl[tid] = 0.0f;
        mrow[tid] = amask[b * 2048 + q0 + tid];
    }

    unsigned long long o2[4][2];
#pragma unroll
    for (int i = 0; i < 4; i++) { o2[i][0] = 0ull; o2[i][1] = 0ull; }

    for (int jt = 0; jt < 32; jt++) {
        const int kbase = (b * 2048 + jt * 64 + lr) * 1024 + h * 64;
        __syncthreads();  // prior PV reads of Kt/Vs/Ss done (also publishes Qt on iter 0)
        // load K (transposed) and V (natural)
#pragma unroll
        for (int t = 0; t < 4; t++) {
            int d4 = (tid & 3) * 4 + t * 16;
            float4 kv = *(const float4*)&g_K[kbase + d4];
            Kt[(d4 + 0) * SPAD + lr] = kv.x;
            Kt[(d4 + 1) * SPAD + lr] = kv.y;
            Kt[(d4 + 2) * SPAD + lr] = kv.z;
            Kt[(d4 + 3) * SPAD + lr] = kv.w;
            float4 vv = *(const float4*)&g_V[kbase + d4];
            *(float4*)&Vs[lr * SPAD + d4] = vv;
        }
        __syncthreads();

        // S = Q @ K^T (f32x2 accumulators, pairs along key cols)
        unsigned long long s2[4][2];
#pragma unroll
        for (int i = 0; i < 4; i++) { s2[i][0] = 0ull; s2[i][1] = 0ull; }
#pragma unroll 8
        for (int d = 0; d < 64; d++) {
            float4 a = *(const float4*)&Qt[d * SPAD + tq];
            float4 bk4 = *(const float4*)&Kt[d * SPAD + tk];
            unsigned long long bb0 = pk2(bk4.x, bk4.y);
            unsigned long long bb1 = pk2(bk4.z, bk4.w);
            float av[4] = {a.x, a.y, a.z, a.w};
#pragma unroll
            for (int i = 0; i < 4; i++) {
                unsigned long long aa = pk2(av[i], av[i]);
                s2[i][0] = ffma2(aa, bb0, s2[i][0]);
                s2[i][1] = ffma2(aa, bb1, s2[i][1]);
            }
        }
        // scale (1/sqrt(64) = 0.125), masked rows -> 0 logits (uniform softmax)
#pragma unroll
        for (int i = 0; i < 4; i++) {
            int q = tq + i;
            float x0, x1, x2, x3;
            upk2(s2[i][0], x0, x1);
            upk2(s2[i][1], x2, x3);
            float4 w;
            if (mrow[q])
                w = make_float4(x0 * 0.125f, x1 * 0.125f, x2 * 0.125f, x3 * 0.125f);
            else
                w = make_float4(0.0f, 0.0f, 0.0f, 0.0f);
            *(float4*)&Ss[q * SPAD + tk] = w;
        }
        __syncthreads();

        // online softmax: warp w owns rows 8w..8w+7
        {
            int w = tid >> 5, lane = tid & 31;
#pragma unroll
            for (int r = 0; r < 8; r++) {
                int q = w * 8 + r;
                float s0 = Ss[q * SPAD + lane];
                float s1 = Ss[q * SPAD + 32 + lane];
                float mx = fmaxf(s0, s1);
#pragma unroll
                for (int o = 16; o > 0; o >>= 1) mx = fmaxf(mx, __shfl_xor_sync(0xffffffffu, mx, o));
                float mold = rowm[q];
                float mnew = fmaxf(mold, mx);
                float p0 = __expf(s0 - mnew);
                float p1 = __expf(s1 - mnew);
                Ss[q * SPAD + lane] = p0;
                Ss[q * SPAD + 32 + lane] = p1;
                float sum = p0 + p1;
#pragma unroll
                for (int o = 16; o > 0; o >>= 1) sum += __shfl_xor_sync(0xffffffffu, sum, o);
                if (lane == 0) {
                    rowc[q] = __expf(mold - mnew);
                    rowl[q] = rowl[q] * rowc[q] + sum;
                    rowm[q] = mnew;
                }
            }
        }
        __syncthreads();

        // rescale O, then O += P @ V
#pragma unroll
        for (int i = 0; i < 4; i++) {
            float c = rowc[tq + i];
            unsigned long long cc = pk2(c, c);
            o2[i][0] = fmul2(o2[i][0], cc);
            o2[i][1] = fmul2(o2[i][1], cc);
        }
#pragma unroll 8
        for (int kk = 0; kk < 64; kk++) {
            float4 v4 = *(const float4*)&Vs[kk * SPAD + tk];
            unsigned long long bb0 = pk2(v4.x, v4.y);
            unsigned long long bb1 = pk2(v4.z, v4.w);
#pragma unroll
            for (int i = 0; i < 4; i++) {
                float a = Ss[(tq + i) * SPAD + kk];
                unsigned long long aa = pk2(a, a);
                o2[i][0] = ffma2(aa, bb0, o2[i][0]);
                o2[i][1] = ffma2(aa, bb1, o2[i][1]);
            }
        }
    }

    __syncthreads();  // all PV reads of Ss done; reuse Ss for the output tile
    // normalized O -> Ss[q][d]
#pragma unroll
    for (int i = 0; i < 4; i++) {
        int q = tq + i;
        float invl = 1.0f / rowl[q];
        float x0, x1, x2, x3;
        upk2(o2[i][0], x0, x1);
        upk2(o2[i][1], x2, x3);
        *(float4*)&Ss[q * SPAD + tk] =
            make_float4(x0 * invl, x1 * invl, x2 * invl, x3 * invl);
    }
    __syncthreads();

    // scrambled reshape + residual:
    //   out[b, 2*(h*64+d) + (q>=1024), q%1024] = O[q][d] + queries[b, same coords]
    const int e = (q0 >= 1024) ? 1 : 0;
    const int dd = tid >> 2;         // d: 0..63 per thread
    const int qq = (tid & 3) * 16;   // 16 consecutive q per thread -> 64B coalesced runs
    const int srow = 128 * h + 2 * dd + e;
    const int col0 = (q0 & 1023) + qq;
    const float* qptr = queries + (b * 2048 + srow) * 1024 + col0;
    float* optr = out + (b * 2048 + srow) * 1024 + col0;
#pragma unroll
    for (int t = 0; t < 16; t += 4) {
        float4 qv = *(const float4*)&qptr[t];
        float4 r;
        r.x = Ss[(qq + t + 0) * SPAD + dd] + qv.x;
        r.y = Ss[(qq + t + 1) * SPAD + dd] + qv.y;
        r.z = Ss[(qq + t + 2) * SPAD + dd] + qv.z;
        r.w = Ss[(qq + t + 3) * SPAD + dd] + qv.w;
        *(float4*)&optr[t] = r;
    }
}

// ---------------- launch ----------------
extern "C" void kernel_launch(void* const* d_in, const int* in_sizes, int n_in, void* d_out,
                              int out_size) {
    const float* queries = (const float*)d_in[0];
    const float* keys = (const float*)d_in[1];
    const float* values = (const float*)d_in[2];
    const int* amask = (const int*)d_in[3];
    const float* Wq = (const float*)d_in[4];
    const float* bq = (const float*)d_in[5];
    const float* Wk = (const float*)d_in[6];
    const float* bk = (const float*)d_in[7];
    const float* Wv = (const float*)d_in[8];
    const float* bv = (const float*)d_in[9];
    float* out = (float*)d_out;

    dim3 g1(8, 32, 3);
    qkv_gemm<<<g1, 256>>>(queries, keys, values, Wq, Wk, Wv, bq, bk, bv);

    cudaFuncSetAttribute(attn_kernel, cudaFuncAttributeMaxDynamicSharedMemorySize, ATTN_SMEM);
    dim3 g2(32, 16, 2);
    attn_kernel<<<g2, 256, ATTN_SMEM>>>(amask, queries, out);
}

// round 2
// speedup vs baseline: 2.1925x; 2.1925x over previous
#include <cuda_runtime.h>

// Problem constants
#define BB 2
#define SS 2048
#define DD 1024
#define HH 16
#define HD 64

// Intermediate Q/K/V buffers (device globals: no allocation allowed)
__device__ float g_Q[BB * SS * DD];
__device__ float g_K[BB * SS * DD];
__device__ float g_V[BB * SS * DD];

// ---- tf32 helpers ----
__device__ __forceinline__ float cvtf(float x) {
    unsigned u;
    asm("cvt.rna.tf32.f32 %0, %1;" : "=r"(u) : "f"(x));
    return __uint_as_float(u);
}
// D = A(16x8 row) * B(8x8 col) + D, tf32 inputs / f32 accum
__device__ __forceinline__ void mma8(float c[4], const unsigned a[4], const unsigned b[2]) {
    asm volatile(
        "mma.sync.aligned.m16n8k8.row.col.f32.tf32.tf32.f32 "
        "{%0,%1,%2,%3},{%4,%5,%6,%7},{%8,%9},{%0,%1,%2,%3};"
        : "+f"(c[0]), "+f"(c[1]), "+f"(c[2]), "+f"(c[3])
        : "r"(a[0]), "r"(a[1]), "r"(a[2]), "r"(a[3]), "r"(b[0]), "r"(b[1]));
}

// =====================================================================
// QKV projection: C[m,n] = relu(sum_k X[m,k]*W[n,k] + bias[n])
// M=4096, N=K=1024. Block 256 thr (8 warps 4x2), tile 128x128, KC=32.
// Warp tile 32x64: 2 mtiles x 8 ntiles of m16n8k8.
// =====================================================================
#define GST 36  // smem row stride (32 + 4): bank = 4*row + k (conflict-free frags)

__global__ void __launch_bounds__(256, 2) qkv_gemm(
    const float* __restrict__ Xq, const float* __restrict__ Xk, const float* __restrict__ Xv,
    const float* __restrict__ Wq, const float* __restrict__ Wk, const float* __restrict__ Wv,
    const float* __restrict__ bq, const float* __restrict__ bk, const float* __restrict__ bv) {
    const float* X;
    const float* W;
    const float* bias;
    float* out;
    if (blockIdx.z == 0)      { X = Xq; W = Wq; bias = bq; out = g_Q; }
    else if (blockIdx.z == 1) { X = Xk; W = Wk; bias = bk; out = g_K; }
    else                      { X = Xv; W = Wv; bias = bv; out = g_V; }

    __shared__ float Xs[128 * GST];
    __shared__ float Ws[128 * GST];

    const int tid = threadIdx.x;
    const int warp = tid >> 5, lane = tid & 31;
    const int g = lane >> 2, tig = lane & 3;
    const int m0 = (warp >> 1) * 32;  // warp m offset in tile
    const int n0 = (warp & 1) * 64;   // warp n offset in tile
    const int bm = blockIdx.y * 128;
    const int bn = blockIdx.x * 128;

    const int lr = tid & 127;          // loader row
    const int lk = (tid >> 7) * 16;    // loader k offset (0/16)

    float acc[2][8][4];
#pragma unroll
    for (int mt = 0; mt < 2; mt++)
#pragma unroll
        for (int nt = 0; nt < 8; nt++)
#pragma unroll
            for (int i = 0; i < 4; i++) acc[mt][nt][i] = 0.0f;

    for (int k0 = 0; k0 < 1024; k0 += 32) {
        float4 xv[4], wv[4];
#pragma unroll
        for (int j = 0; j < 4; j++) {
            xv[j] = *(const float4*)&X[(size_t)(bm + lr) * 1024 + k0 + lk + 4 * j];
            wv[j] = *(const float4*)&W[(size_t)(bn + lr) * 1024 + k0 + lk + 4 * j];
        }
        __syncthreads();
#pragma unroll
        for (int j = 0; j < 4; j++) {
            *(float4*)&Xs[lr * GST + lk + 4 * j] =
                make_float4(cvtf(xv[j].x), cvtf(xv[j].y), cvtf(xv[j].z), cvtf(xv[j].w));
            *(float4*)&Ws[lr * GST + lk + 4 * j] =
                make_float4(cvtf(wv[j].x), cvtf(wv[j].y), cvtf(wv[j].z), cvtf(wv[j].w));
        }
        __syncthreads();

#pragma unroll
        for (int ks = 0; ks < 4; ks++) {
            unsigned a[2][4];
#pragma unroll
            for (int mt = 0; mt < 2; mt++) {
                int r = (m0 + 16 * mt + g) * GST + ks * 8;
                a[mt][0] = __float_as_uint(Xs[r + tig]);
                a[mt][1] = __float_as_uint(Xs[r + 8 * GST + tig]);
                a[mt][2] = __float_as_uint(Xs[r + tig + 4]);
                a[mt][3] = __float_as_uint(Xs[r + 8 * GST + tig + 4]);
            }
#pragma unroll
            for (int nt = 0; nt < 8; nt++) {
                int r = (n0 + 8 * nt + g) * GST + ks * 8;
                unsigned b[2];
                b[0] = __float_as_uint(Ws[r + tig]);
                b[1] = __float_as_uint(Ws[r + tig + 4]);
                mma8(acc[0][nt], a[0], b);
                mma8(acc[1][nt], a[1], b);
            }
        }
    }

    // epilogue: bias + relu + store (float2 per frag row)
#pragma unroll
    for (int nt = 0; nt < 8; nt++) {
        int n = bn + n0 + 8 * nt + 2 * tig;
        float b0 = __ldg(&bias[n]), b1 = __ldg(&bias[n + 1]);
#pragma unroll
        for (int mt = 0; mt < 2; mt++) {
            int m = bm + m0 + 16 * mt + g;
            float v0 = acc[mt][nt][0] + b0, v1 = acc[mt][nt][1] + b1;
            v0 = v0 > 0.f ? v0 : 0.f;
            v1 = v1 > 0.f ? v1 : 0.f;
            *(float2*)&out[(size_t)m * 1024 + n] = make_float2(v0, v1);
            float v2 = acc[mt][nt][2] + b0, v3 = acc[mt][nt][3] + b1;
            v2 = v2 > 0.f ? v2 : 0.f;
            v3 = v3 > 0.f ? v3 : 0.f;
            *(float2*)&out[(size_t)(m + 8) * 1024 + n] = make_float2(v2, v3);
        }
    }
}

// =====================================================================
// Flash attention (tf32 mma) + scrambled-reshape epilogue + residual.
// Block: 256 thr (8 warps), 128-query tile, loop over 32 key tiles of 64.
// Warp owns 16 q rows; softmax in registers via quad-lane shuffles.
// =====================================================================
#define AST 68  // smem row stride for 64-wide tiles: bank = 4*row + col

#define ATTN_SMEM ((64 + 64 + 128) * AST * 4)

__global__ void __launch_bounds__(256) attn_mma(const int* __restrict__ amask,
                                                const float* __restrict__ queries,
                                                float* __restrict__ out) {
    extern __shared__ float sm[];
    float* Ks = sm;                 // [key][d]   64 x AST
    float* Vt = sm + 64 * AST;      // [d][key]   64 x AST (transposed)
    float* Ps = sm + 128 * AST;     // [q][*]     128 x AST (Q stage -> P -> O)

    const int tid = threadIdx.x;
    const int warp = tid >> 5, lane = tid & 31;
    const int g = lane >> 2, tig = lane & 3;
    const int b = blockIdx.z, h = blockIdx.y;
    const int q0 = blockIdx.x * 128;
    const int qw = warp * 16;  // warp's q offset within tile

    // ---- stage Q (pre-scaled by 1/sqrt(64)=0.125, tf32-rounded) ----
    {
        int lr = tid & 127;
        int lc = (tid >> 7) * 32;
        const float* qsrc = g_Q + (size_t)(b * 2048 + q0 + lr) * 1024 + h * 64 + lc;
#pragma unroll
        for (int j = 0; j < 8; j++) {
            float4 v = *(const float4*)&qsrc[4 * j];
            *(float4*)&Ps[lr * AST + lc + 4 * j] =
                make_float4(cvtf(0.125f * v.x), cvtf(0.125f * v.y), cvtf(0.125f * v.z),
                            cvtf(0.125f * v.w));
        }
    }
    // per-thread row masks (rows g and g+8 of warp's 16)
    const float fA = (amask[b * 2048 + q0 + qw + g] != 0) ? 1.0f : 0.0f;
    const float fB = (amask[b * 2048 + q0 + qw + g + 8] != 0) ? 1.0f : 0.0f;
    __syncthreads();

    // ---- Q fragments into registers (8 ksteps x 4 regs) ----
    unsigned qf[8][4];
#pragma unroll
    for (int ks = 0; ks < 8; ks++) {
        int r = (qw + g) * AST + ks * 8;
        qf[ks][0] = __float_as_uint(Ps[r + tig]);
        qf[ks][1] = __float_as_uint(Ps[r + 8 * AST + tig]);
        qf[ks][2] = __float_as_uint(Ps[r + tig + 4]);
        qf[ks][3] = __float_as_uint(Ps[r + 8 * AST + tig + 4]);
    }

    float mA = -1e30f, mB = -1e30f, lA = 0.0f, lB = 0.0f;
    float o[8][4];
#pragma unroll
    for (int nt = 0; nt < 8; nt++)
#pragma unroll
        for (int i = 0; i < 4; i++) o[nt][i] = 0.0f;

    const int key = tid & 63;
    const int dbase = (tid >> 6) * 16;

    for (int jt = 0; jt < 32; jt++) {
        __syncthreads();  // Ks/Vt reads of prior iter done (and Q-frag LDS on iter 0)
        // ---- stage K (natural) and V (transposed), tf32-rounded ----
        {
            const size_t src = (size_t)(b * 2048 + jt * 64 + key) * 1024 + h * 64 + dbase;
            const float* ksrc = g_K + src;
            const float* vsrc = g_V + src;
#pragma unroll
            for (int j = 0; j < 4; j++) {
                float4 kv = *(const float4*)&ksrc[4 * j];
                *(float4*)&Ks[key * AST + dbase + 4 * j] =
                    make_float4(cvtf(kv.x), cvtf(kv.y), cvtf(kv.z), cvtf(kv.w));
                float4 vv = *(const float4*)&vsrc[4 * j];
                Vt[(dbase + 4 * j + 0) * AST + key] = cvtf(vv.x);
                Vt[(dbase + 4 * j + 1) * AST + key] = cvtf(vv.y);
                Vt[(dbase + 4 * j + 2) * AST + key] = cvtf(vv.z);
                Vt[(dbase + 4 * j + 3) * AST + key] = cvtf(vv.w);
            }
        }
        __syncthreads();

        // ---- S = Q @ K^T (per warp: 16 x 64), mask by multiply ----
        float s[8][4];
#pragma unroll
        for (int nt = 0; nt < 8; nt++)
#pragma unroll
            for (int i = 0; i < 4; i++) s[nt][i] = 0.0f;
#pragma unroll
        for (int ks = 0; ks < 8; ks++) {
#pragma unroll
            for (int nt = 0; nt < 8; nt++) {
                int r = (8 * nt + g) * AST + ks * 8;
                unsigned kb[2];
                kb[0] = __float_as_uint(Ks[r + tig]);
                kb[1] = __float_as_uint(Ks[r + tig + 4]);
                mma8(s[nt], qf[ks], kb);
            }
        }
#pragma unroll
        for (int nt = 0; nt < 8; nt++) {
            s[nt][0] *= fA; s[nt][1] *= fA;
            s[nt][2] *= fB; s[nt][3] *= fB;
        }

        // ---- online softmax (registers + quad shuffles) ----
        float mxA = s[0][0], mxB = s[0][2];
#pragma unroll
        for (int nt = 0; nt < 8; nt++) {
            mxA = fmaxf(mxA, fmaxf(s[nt][0], s[nt][1]));
            mxB = fmaxf(mxB, fmaxf(s[nt][2], s[nt][3]));
        }
        mxA = fmaxf(mxA, __shfl_xor_sync(0xffffffffu, mxA, 1));
        mxA = fmaxf(mxA, __shfl_xor_sync(0xffffffffu, mxA, 2));
        mxB = fmaxf(mxB, __shfl_xor_sync(0xffffffffu, mxB, 1));
        mxB = fmaxf(mxB, __shfl_xor_sync(0xffffffffu, mxB, 2));
        float mnA = fmaxf(mA, mxA), mnB = fmaxf(mB, mxB);
        float cA = __expf(mA - mnA), cB = __expf(mB - mnB);
        mA = mnA; mB = mnB;
        float sumA = 0.0f, sumB = 0.0f;
#pragma unroll
        for (int nt = 0; nt < 8; nt++) {
            s[nt][0] = __expf(s[nt][0] - mnA);
            s[nt][1] = __expf(s[nt][1] - mnA);
            s[nt][2] = __expf(s[nt][2] - mnB);
            s[nt][3] = __expf(s[nt][3] - mnB);
            sumA += s[nt][0] + s[nt][1];
            sumB += s[nt][2] + s[nt][3];
        }
        sumA += __shfl_xor_sync(0xffffffffu, sumA, 1);
        sumA += __shfl_xor_sync(0xffffffffu, sumA, 2);
        sumB += __shfl_xor_sync(0xffffffffu, sumB, 1);
        sumB += __shfl_xor_sync(0xffffffffu, sumB, 2);
        lA = lA * cA + sumA;
        lB = lB * cB + sumB;

        // ---- P -> smem (warp-local rows; tf32-rounded), rescale O ----
        __syncwarp();
#pragma unroll
        for (int nt = 0; nt < 8; nt++) {
            *(float2*)&Ps[(qw + g) * AST + 8 * nt + 2 * tig] =
                make_float2(cvtf(s[nt][0]), cvtf(s[nt][1]));
            *(float2*)&Ps[(qw + g + 8) * AST + 8 * nt + 2 * tig] =
                make_float2(cvtf(s[nt][2]), cvtf(s[nt][3]));
        }
#pragma unroll
        for (int nt = 0; nt < 8; nt++) {
            o[nt][0] *= cA; o[nt][1] *= cA;
            o[nt][2] *= cB; o[nt][3] *= cB;
        }
        __syncwarp();

        // ---- O += P @ V ----
#pragma unroll
        for (int ks = 0; ks < 8; ks++) {
            unsigned pa[4];
            int r = (qw + g) * AST + ks * 8;
            pa[0] = __float_as_uint(Ps[r + tig]);
            pa[1] = __float_as_uint(Ps[r + 8 * AST + tig]);
            pa[2] = __float_as_uint(Ps[r + tig + 4]);
            pa[3] = __float_as_uint(Ps[r + 8 * AST + tig + 4]);
#pragma unroll
            for (int nt = 0; nt < 8; nt++) {
                int v = (8 * nt + g) * AST + ks * 8;
                unsigned vb[2];
                vb[0] = __float_as_uint(Vt[v + tig]);
                vb[1] = __float_as_uint(Vt[v + tig + 4]);
                mma8(o[nt], pa, vb);
            }
        }
    }

    // ---- normalize and park O in smem (warp-local rows) ----
    {
        float rA = 1.0f / lA, rB = 1.0f / lB;
        __syncwarp();
#pragma unroll
        for (int nt = 0; nt < 8; nt++) {
            *(float2*)&Ps[(qw + g) * AST + 8 * nt + 2 * tig] =
                make_float2(o[nt][0] * rA, o[nt][1] * rA);
            *(float2*)&Ps[(qw + g + 8) * AST + 8 * nt + 2 * tig] =
                make_float2(o[nt][2] * rB, o[nt][3] * rB);
        }
    }
    __syncthreads();

    // ---- scrambled reshape + residual:
    //   out[b, 128h + 2d + e, q % 1024] = O[q][d] + queries[...], e = (q >= 1024)
    const int e = (q0 >= 1024) ? 1 : 0;
    const int dd = tid >> 2;
    const int qq = (tid & 3) * 16;
    const int srow = 128 * h + 2 * dd + e;
    const int col0 = q0 & 1023;
    const float* qp = queries + (size_t)(b * 2048 + srow) * 1024 + col0;
    float* op = out + (size_t)(b * 2048 + srow) * 1024 + col0;
#pragma unroll
    for (int half = 0; half < 128; half += 64) {
#pragma unroll
        for (int t = 0; t < 16; t += 4) {
            int ql = half + qq + t;
            float4 qv = *(const float4*)&qp[ql];
            float4 r;
            r.x = Ps[(ql + 0) * AST + dd] + qv.x;
            r.y = Ps[(ql + 1) * AST + dd] + qv.y;
            r.z = Ps[(ql + 2) * AST + dd] + qv.z;
            r.w = Ps[(ql + 3) * AST + dd] + qv.w;
            *(float4*)&op[ql] = r;
        }
    }
}

// ---------------- launch ----------------
extern "C" void kernel_launch(void* const* d_in, const int* in_sizes, int n_in, void* d_out,
                              int out_size) {
    const float* queries = (const float*)d_in[0];
    const float* keys = (const float*)d_in[1];
    const float* values = (const float*)d_in[2];
    const int* amask = (const int*)d_in[3];
    const float* Wq = (const float*)d_in[4];
    const float* bq = (const float*)d_in[5];
    const float* Wk = (const float*)d_in[6];
    const float* bk = (const float*)d_in[7];
    const float* Wv = (const float*)d_in[8];
    const float* bv = (const float*)d_in[9];
    float* out = (float*)d_out;

    dim3 g1(8, 32, 3);
    qkv_gemm<<<g1, 256>>>(queries, keys, values, Wq, Wk, Wv, bq, bk, bv);

    cudaFuncSetAttribute(attn_mma, cudaFuncAttributeMaxDynamicSharedMemorySize, ATTN_SMEM);
    dim3 g2(16, 16, 2);
    attn_mma<<<g2, 256, ATTN_SMEM>>>(amask, queries, out);
}

// round 3
// speedup vs baseline: 3.8407x; 1.7517x over previous
#include <cuda_runtime.h>
#include <cuda_fp16.h>

// Problem constants
#define BB 2
#define SS 2048
#define DD 1024

// Intermediate Q/K/V buffers in fp16 (device globals: no allocation allowed)
__device__ __half g_Q[BB * SS * DD];
__device__ __half g_K[BB * SS * DD];
__device__ __half g_V[BB * SS * DD];

// ---------- helpers ----------
__device__ __forceinline__ unsigned sptr(const void* p) {
    return (unsigned)__cvta_generic_to_shared(p);
}
__device__ __forceinline__ void ldsm4(unsigned& r0, unsigned& r1, unsigned& r2, unsigned& r3,
                                      unsigned addr) {
    asm volatile("ldmatrix.sync.aligned.m8n8.x4.shared.b16 {%0,%1,%2,%3}, [%4];"
                 : "=r"(r0), "=r"(r1), "=r"(r2), "=r"(r3)
                 : "r"(addr));
}
__device__ __forceinline__ void ldsm4t(unsigned& r0, unsigned& r1, unsigned& r2, unsigned& r3,
                                       unsigned addr) {
    asm volatile("ldmatrix.sync.aligned.m8n8.x4.trans.shared.b16 {%0,%1,%2,%3}, [%4];"
                 : "=r"(r0), "=r"(r1), "=r"(r2), "=r"(r3)
                 : "r"(addr));
}
// D(16x8,f32) += A(16x16,f16) * B(16x8,f16)
__device__ __forceinline__ void mma16(float c[4], const unsigned a[4], unsigned b0, unsigned b1) {
    asm volatile(
        "mma.sync.aligned.m16n8k16.row.col.f32.f16.f16.f32 "
        "{%0,%1,%2,%3},{%4,%5,%6,%7},{%8,%9},{%0,%1,%2,%3};"
        : "+f"(c[0]), "+f"(c[1]), "+f"(c[2]), "+f"(c[3])
        : "r"(a[0]), "r"(a[1]), "r"(a[2]), "r"(a[3]), "r"(b0), "r"(b1));
}

// =====================================================================
// QKV projection: out[m,n] = relu(sum_k X[m,k]*W[n,k] + bias[n]) -> fp16
// M=4096, N=K=1024. 256 thr (8 warps 4x2), tile 128x128, kc=32, fp16 mma.
// =====================================================================
#define GST 40  // halves per smem row (80B = 20 banks: 8 consecutive rows conflict-free)

__global__ void __launch_bounds__(256, 2) qkv_gemm(
    const float* __restrict__ Xq, const float* __restrict__ Xk, const float* __restrict__ Xv,
    const float* __restrict__ Wq, const float* __restrict__ Wk, const float* __restrict__ Wv,
    const float* __restrict__ bq, const float* __restrict__ bk, const float* __restrict__ bv) {
    const float* X;
    const float* W;
    const float* bias;
    __half* out;
    if (blockIdx.z == 0)      { X = Xq; W = Wq; bias = bq; out = g_Q; }
    else if (blockIdx.z == 1) { X = Xk; W = Wk; bias = bk; out = g_K; }
    else                      { X = Xv; W = Wv; bias = bv; out = g_V; }

    __shared__ __align__(16) __half Xs[128 * GST];
    __shared__ __align__(16) __half Ws[128 * GST];

    const int tid = threadIdx.x;
    const int warp = tid >> 5, lane = tid & 31;
    const int g = lane >> 2, tig = lane & 3;
    const int m0 = (warp >> 1) * 32;
    const int n0 = (warp & 1) * 64;
    const int bm = blockIdx.y * 128;
    const int bn = blockIdx.x * 128;

    const int lr = tid & 127;        // loader row
    const int lk = (tid >> 7) * 16;  // loader k offset (halves)

    float acc[2][8][4];
#pragma unroll
    for (int mt = 0; mt < 2; mt++)
#pragma unroll
        for (int nt = 0; nt < 8; nt++)
#pragma unroll
            for (int i = 0; i < 4; i++) acc[mt][nt][i] = 0.0f;

    // fragment addresses (lane-dependent, loop-invariant except k-step offset)
    const unsigned xa0 = sptr(&Xs[(m0 + (lane & 15)) * GST + (lane >> 4) * 8]);
    const unsigned xa1 = sptr(&Xs[(m0 + 16 + (lane & 15)) * GST + (lane >> 4) * 8]);
    const unsigned wb = sptr(&Ws[(n0 + 8 * (lane >> 4) + (lane & 7)) * GST + ((lane >> 3) & 1) * 8]);

    for (int k0 = 0; k0 < 1024; k0 += 32) {
        float4 xv[4], wv[4];
#pragma unroll
        for (int j = 0; j < 4; j++) {
            xv[j] = *(const float4*)&X[(size_t)(bm + lr) * 1024 + k0 + lk + 4 * j];
            wv[j] = *(const float4*)&W[(size_t)(bn + lr) * 1024 + k0 + lk + 4 * j];
        }
        __syncthreads();
        {
            __half2 hx[8], hw[8];
#pragma unroll
            for (int j = 0; j < 4; j++) {
                hx[2 * j] = __floats2half2_rn(xv[j].x, xv[j].y);
                hx[2 * j + 1] = __floats2half2_rn(xv[j].z, xv[j].w);
                hw[2 * j] = __floats2half2_rn(wv[j].x, wv[j].y);
                hw[2 * j + 1] = __floats2half2_rn(wv[j].z, wv[j].w);
            }
            *(uint4*)&Xs[lr * GST + lk] = *(uint4*)&hx[0];
            *(uint4*)&Xs[lr * GST + lk + 8] = *(uint4*)&hx[4];
            *(uint4*)&Ws[lr * GST + lk] = *(uint4*)&hw[0];
            *(uint4*)&Ws[lr * GST + lk + 8] = *(uint4*)&hw[4];
        }
        __syncthreads();

#pragma unroll
        for (int ks = 0; ks < 2; ks++) {
            unsigned a0[4], a1[4];
            ldsm4(a0[0], a0[1], a0[2], a0[3], xa0 + ks * 32);
            ldsm4(a1[0], a1[1], a1[2], a1[3], xa1 + ks * 32);
#pragma unroll
            for (int j = 0; j < 4; j++) {
                unsigned b[4];
                ldsm4(b[0], b[1], b[2], b[3], wb + j * 16 * GST * 2 + ks * 32);
                mma16(acc[0][2 * j], a0, b[0], b[1]);
                mma16(acc[0][2 * j + 1], a0, b[2], b[3]);
                mma16(acc[1][2 * j], a1, b[0], b[1]);
                mma16(acc[1][2 * j + 1], a1, b[2], b[3]);
            }
        }
    }

    // epilogue: bias + relu + fp16 store
#pragma unroll
    for (int nt = 0; nt < 8; nt++) {
        int n = bn + n0 + 8 * nt + 2 * tig;
        float b0 = __ldg(&bias[n]), b1 = __ldg(&bias[n + 1]);
#pragma unroll
        for (int mt = 0; mt < 2; mt++) {
            int m = bm + m0 + 16 * mt + g;
            float v0 = acc[mt][nt][0] + b0, v1 = acc[mt][nt][1] + b1;
            v0 = v0 > 0.f ? v0 : 0.f;
            v1 = v1 > 0.f ? v1 : 0.f;
            *(__half2*)&out[(size_t)m * 1024 + n] = __floats2half2_rn(v0, v1);
            float v2 = acc[mt][nt][2] + b0, v3 = acc[mt][nt][3] + b1;
            v2 = v2 > 0.f ? v2 : 0.f;
            v3 = v3 > 0.f ? v3 : 0.f;
            *(__half2*)&out[(size_t)(m + 8) * 1024 + n] = __floats2half2_rn(v2, v3);
        }
    }
}

// =====================================================================
// Flash attention (fp16 mma + ldmatrix) + scrambled reshape + residual.
// 256 thr (8 warps), 128-query tile, 32 key tiles of 64. Softmax in regs.
// =====================================================================
#define KST 72  // halves per smem row (144B = 36 banks: conflict-free LDSM)
#define OST 68  // floats per row of the final O overlay
// layout: Ks[64*KST]h (9216B) | Vs[64*KST]h (9216B) | Ps[128*KST]h (18432B)
#define OFF_V (64 * KST * 2)
#define OFF_P (128 * KST * 2)
#define ATTN_SMEM (256 * KST * 2)  // 36864B; O overlay (128*OST*4=34816B) fits

__global__ void __launch_bounds__(256) attn_mma(const int* __restrict__ amask,
                                                const float* __restrict__ queries,
                                                float* __restrict__ out) {
    extern __shared__ __align__(16) char smbase[];
    __half* Ks = (__half*)smbase;
    __half* Vs = (__half*)(smbase + OFF_V);
    __half* Ps = (__half*)(smbase + OFF_P);
    float* So = (float*)smbase;

    const int tid = threadIdx.x;
    const int warp = tid >> 5, lane = tid & 31;
    const int g = lane >> 2, tig = lane & 3;
    const int b = blockIdx.z, h = blockIdx.y;
    const int q0 = blockIdx.x * 128;
    const int qw = warp * 16;

    // ---- stage Q (scaled by exact 0.125) into Ps, then frags to registers ----
    {
        int row = tid >> 1;
        int koff = (tid & 1) * 32;  // halves
        const __half* qsrc = g_Q + (size_t)(b * 2048 + q0 + row) * 1024 + h * 64 + koff;
        const __half2 sc = __floats2half2_rn(0.125f, 0.125f);
        __half2 v[16];
        *(uint4*)&v[0] = *(const uint4*)&qsrc[0];
        *(uint4*)&v[4] = *(const uint4*)&qsrc[8];
        *(uint4*)&v[8] = *(const uint4*)&qsrc[16];
        *(uint4*)&v[12] = *(const uint4*)&qsrc[24];
#pragma unroll
        for (int j = 0; j < 16; j++) v[j] = __hmul2(v[j], sc);
        *(uint4*)&Ps[row * KST + koff] = *(uint4*)&v[0];
        *(uint4*)&Ps[row * KST + koff + 8] = *(uint4*)&v[4];
        *(uint4*)&Ps[row * KST + koff + 16] = *(uint4*)&v[8];
        *(uint4*)&Ps[row * KST + koff + 24] = *(uint4*)&v[12];
    }
    const float fA = (amask[b * 2048 + q0 + qw + g] != 0) ? 1.0f : 0.0f;
    const float fB = (amask[b * 2048 + q0 + qw + g + 8] != 0) ? 1.0f : 0.0f;
    __syncthreads();

    unsigned qf[4][4];
    {
        unsigned qa = sptr(&Ps[(qw + (lane & 15)) * KST + (lane >> 4) * 8]);
#pragma unroll
        for (int ks = 0; ks < 4; ks++)
            ldsm4(qf[ks][0], qf[ks][1], qf[ks][2], qf[ks][3], qa + ks * 32);
    }

    float mA = -1e30f, mB = -1e30f, lA = 0.0f, lB = 0.0f;
    float o[8][4];
#pragma unroll
    for (int nt = 0; nt < 8; nt++)
#pragma unroll
        for (int i = 0; i < 4; i++) o[nt][i] = 0.0f;

    // loader mapping: row = tid>>2 (0..63), koff = (tid&3)*16 halves
    const int vrow = tid >> 2;
    const int vkoff = (tid & 3) * 16;

    // lane-dependent LDSM base addresses
    const unsigned kb_base = sptr(&Ks[(8 * (lane >> 4) + (lane & 7)) * KST + ((lane >> 3) & 1) * 8]);
    const unsigned pa_base = sptr(&Ps[(qw + (lane & 15)) * KST + (lane >> 4) * 8]);
    const unsigned vb_base = sptr(&Vs[(8 * ((lane >> 3) & 1) + (lane & 7)) * KST + (lane >> 4) * 8]);

    for (int jt = 0; jt < 32; jt++) {
        __syncthreads();  // previous tile's reads of Ks/Vs (and Q-frag LDSM on iter 0) done
        {
            const size_t src = (size_t)(b * 2048 + jt * 64 + vrow) * 1024 + h * 64 + vkoff;
            uint4 k0 = *(const uint4*)&g_K[src];
            uint4 k1 = *(const uint4*)&g_K[src + 8];
            uint4 v0 = *(const uint4*)&g_V[src];
            uint4 v1 = *(const uint4*)&g_V[src + 8];
            *(uint4*)&Ks[vrow * KST + vkoff] = k0;
            *(uint4*)&Ks[vrow * KST + vkoff + 8] = k1;
            *(uint4*)&Vs[vrow * KST + vkoff] = v0;
            *(uint4*)&Vs[vrow * KST + vkoff + 8] = v1;
        }
        __syncthreads();

        // ---- S = Q @ K^T (16q x 64k per warp) ----
        float s[8][4];
#pragma unroll
        for (int nt = 0; nt < 8; nt++)
#pragma unroll
            for (int i = 0; i < 4; i++) s[nt][i] = 0.0f;
#pragma unroll
        for (int ks = 0; ks < 4; ks++) {
#pragma unroll
            for (int j = 0; j < 4; j++) {
                unsigned bfr[4];
                ldsm4(bfr[0], bfr[1], bfr[2], bfr[3], kb_base + j * (16 * KST * 2) + ks * 32);
                mma16(s[2 * j], qf[ks], bfr[0], bfr[1]);
                mma16(s[2 * j + 1], qf[ks], bfr[2], bfr[3]);
            }
        }
#pragma unroll
        for (int nt = 0; nt < 8; nt++) {
            s[nt][0] *= fA; s[nt][1] *= fA;
            s[nt][2] *= fB; s[nt][3] *= fB;
        }

        // ---- online softmax in registers (quad shuffles) ----
        float mxA = s[0][0], mxB = s[0][2];
#pragma unroll
        for (int nt = 0; nt < 8; nt++) {
            mxA = fmaxf(mxA, fmaxf(s[nt][0], s[nt][1]));
            mxB = fmaxf(mxB, fmaxf(s[nt][2], s[nt][3]));
        }
        mxA = fmaxf(mxA, __shfl_xor_sync(0xffffffffu, mxA, 1));
        mxA = fmaxf(mxA, __shfl_xor_sync(0xffffffffu, mxA, 2));
        mxB = fmaxf(mxB, __shfl_xor_sync(0xffffffffu, mxB, 1));
        mxB = fmaxf(mxB, __shfl_xor_sync(0xffffffffu, mxB, 2));
        float mnA = fmaxf(mA, mxA), mnB = fmaxf(mB, mxB);
        float cA = __expf(mA - mnA), cB = __expf(mB - mnB);
        mA = mnA; mB = mnB;
        float sumA = 0.0f, sumB = 0.0f;
#pragma unroll
        for (int nt = 0; nt < 8; nt++) {
            s[nt][0] = __expf(s[nt][0] - mnA);
            s[nt][1] = __expf(s[nt][1] - mnA);
            s[nt][2] = __expf(s[nt][2] - mnB);
            s[nt][3] = __expf(s[nt][3] - mnB);
            sumA += s[nt][0] + s[nt][1];
            sumB += s[nt][2] + s[nt][3];
        }
        sumA += __shfl_xor_sync(0xffffffffu, sumA, 1);
        sumA += __shfl_xor_sync(0xffffffffu, sumA, 2);
        sumB += __shfl_xor_sync(0xffffffffu, sumB, 1);
        sumB += __shfl_xor_sync(0xffffffffu, sumB, 2);
        lA = lA * cA + sumA;
        lB = lB * cB + sumB;

        // ---- P (fp16) to warp-local smem rows; rescale O ----
        __syncwarp();
#pragma unroll
        for (int nt = 0; nt < 8; nt++) {
            *(__half2*)&Ps[(qw + g) * KST + 8 * nt + 2 * tig] = __floats2half2_rn(s[nt][0], s[nt][1]);
            *(__half2*)&Ps[(qw + g + 8) * KST + 8 * nt + 2 * tig] = __floats2half2_rn(s[nt][2], s[nt][3]);
        }
#pragma unroll
        for (int nt = 0; nt < 8; nt++) {
            o[nt][0] *= cA; o[nt][1] *= cA;
            o[nt][2] *= cB; o[nt][3] *= cB;
        }
        __syncwarp();

        // ---- O += P @ V  (V via ldmatrix.trans, no explicit transpose) ----
#pragma unroll
        for (int ks = 0; ks < 4; ks++) {
            unsigned pa[4];
            ldsm4(pa[0], pa[1], pa[2], pa[3], pa_base + ks * 32);
#pragma unroll
            for (int j = 0; j < 4; j++) {
                unsigned vb[4];
                ldsm4t(vb[0], vb[1], vb[2], vb[3], vb_base + ks * (16 * KST * 2) + j * 32);
                mma16(o[2 * j], pa, vb[0], vb[1]);
                mma16(o[2 * j + 1], pa, vb[2], vb[3]);
            }
        }
    }

    __syncthreads();  // all PV reads done; overlay fp32 O on the whole smem region
    {
        float rA = 1.0f / lA, rB = 1.0f / lB;
#pragma unroll
        for (int nt = 0; nt < 8; nt++) {
            *(float2*)&So[(qw + g) * OST + 8 * nt + 2 * tig] =
                make_float2(o[nt][0] * rA, o[nt][1] * rA);
            *(float2*)&So[(qw + g + 8) * OST + 8 * nt + 2 * tig] =
                make_float2(o[nt][2] * rB, o[nt][3] * rB);
        }
    }
    __syncthreads();

    // ---- scrambled reshape + residual:
    //   out[b, 128h + 2d + e, q % 1024] = O[q][d] + queries[...], e = (q0 >= 1024)
    const int e = (q0 >= 1024) ? 1 : 0;
    const int dd = tid >> 2;
    const int qq = (tid & 3) * 16;
    const int srow = 128 * h + 2 * dd + e;
    const int col0 = q0 & 1023;
    const float* qp = queries + (size_t)(b * 2048 + srow) * 1024 + col0;
    float* op = out + (size_t)(b * 2048 + srow) * 1024 + col0;
#pragma unroll
    for (int half = 0; half < 128; half += 64) {
#pragma unroll
        for (int t = 0; t < 16; t += 4) {
            int ql = half + qq + t;
            float4 qv = *(const float4*)&qp[ql];
            float4 r;
            r.x = So[(ql + 0) * OST + dd] + qv.x;
            r.y = So[(ql + 1) * OST + dd] + qv.y;
            r.z = So[(ql + 2) * OST + dd] + qv.z;
            r.w = So[(ql + 3) * OST + dd] + qv.w;
            *(float4*)&op[ql] = r;
        }
    }
}

// ---------------- launch ----------------
extern "C" void kernel_launch(void* const* d_in, const int* in_sizes, int n_in, void* d_out,
                              int out_size) {
    const float* queries = (const float*)d_in[0];
    const float* keys = (const float*)d_in[1];
    const float* values = (const float*)d_in[2];
    const int* amask = (const int*)d_in[3];
    const float* Wq = (const float*)d_in[4];
    const float* bq = (const float*)d_in[5];
    const float* Wk = (const float*)d_in[6];
    const float* bk = (const float*)d_in[7];
    const float* Wv = (const float*)d_in[8];
    const float* bv = (const float*)d_in[9];
    float* out = (float*)d_out;

    dim3 g1(8, 32, 3);
    qkv_gemm<<<g1, 256>>>(queries, keys, values, Wq, Wk, Wv, bq, bk, bv);

    cudaFuncSetAttribute(attn_mma, cudaFuncAttributeMaxDynamicSharedMemorySize, ATTN_SMEM);
    dim3 g2(16, 16, 2);
    attn_mma<<<g2, 256, ATTN_SMEM>>>(amask, queries, out);
}

// round 4
// speedup vs baseline: 4.1478x; 1.0800x over previous
#include <cuda_runtime.h>
#include <cuda_fp16.h>

// Problem constants
#define BB 2
#define SS 2048
#define DD 1024

// Intermediate Q/K/V buffers in fp16 (device globals: no allocation allowed)
__device__ __half g_Q[BB * SS * DD];
__device__ __half g_K[BB * SS * DD];
__device__ __half g_V[BB * SS * DD];

// ---------- helpers ----------
__device__ __forceinline__ unsigned sptr(const void* p) {
    return (unsigned)__cvta_generic_to_shared(p);
}
__device__ __forceinline__ void ldsm4(unsigned& r0, unsigned& r1, unsigned& r2, unsigned& r3,
                                      unsigned addr) {
    asm volatile("ldmatrix.sync.aligned.m8n8.x4.shared.b16 {%0,%1,%2,%3}, [%4];"
                 : "=r"(r0), "=r"(r1), "=r"(r2), "=r"(r3)
                 : "r"(addr));
}
__device__ __forceinline__ void ldsm4t(unsigned& r0, unsigned& r1, unsigned& r2, unsigned& r3,
                                       unsigned addr) {
    asm volatile("ldmatrix.sync.aligned.m8n8.x4.trans.shared.b16 {%0,%1,%2,%3}, [%4];"
                 : "=r"(r0), "=r"(r1), "=r"(r2), "=r"(r3)
                 : "r"(addr));
}
// D(16x8,f32) += A(16x16,f16) * B(16x8,f16)
__device__ __forceinline__ void mma16(float c[4], const unsigned a[4], unsigned b0, unsigned b1) {
    asm volatile(
        "mma.sync.aligned.m16n8k16.row.col.f32.f16.f16.f32 "
        "{%0,%1,%2,%3},{%4,%5,%6,%7},{%8,%9},{%0,%1,%2,%3};"
        : "+f"(c[0]), "+f"(c[1]), "+f"(c[2]), "+f"(c[3])
        : "r"(a[0]), "r"(a[1]), "r"(a[2]), "r"(a[3]), "r"(b0), "r"(b1));
}
__device__ __forceinline__ void cpa16(unsigned s, const void* g) {
    asm volatile("cp.async.cg.shared.global [%0], [%1], 16;" ::"r"(s), "l"(g));
}
__device__ __forceinline__ unsigned h2u(float a, float b) {
    __half2 h = __floats2half2_rn(a, b);
    return *(unsigned*)&h;
}

// =====================================================================
// QKV projection: out[m,n] = relu(sum_k X[m,k]*W[n,k] + bias[n]) -> fp16
// M=4096, N=K=1024. 256 thr (8 warps 4x2), tile 128x128, kc=32.
// Register-prefetch software pipeline: LDG of tile k+1 overlaps mma of k.
// =====================================================================
#define GST 40  // halves per smem row (80B = 20 banks: conflict-free LDSM)

__global__ void __launch_bounds__(256, 2) qkv_gemm(
    const float* __restrict__ Xq, const float* __restrict__ Xk, const float* __restrict__ Xv,
    const float* __restrict__ Wq, const float* __restrict__ Wk, const float* __restrict__ Wv,
    const float* __restrict__ bq, const float* __restrict__ bk, const float* __restrict__ bv) {
    const float* X;
    const float* W;
    const float* bias;
    __half* out;
    if (blockIdx.z == 0)      { X = Xq; W = Wq; bias = bq; out = g_Q; }
    else if (blockIdx.z == 1) { X = Xk; W = Wk; bias = bk; out = g_K; }
    else                      { X = Xv; W = Wv; bias = bv; out = g_V; }

    __shared__ __align__(16) __half Xs[128 * GST];
    __shared__ __align__(16) __half Ws[128 * GST];

    const int tid = threadIdx.x;
    const int warp = tid >> 5, lane = tid & 31;
    const int g = lane >> 2, tig = lane & 3;
    const int m0 = (warp >> 1) * 32;
    const int n0 = (warp & 1) * 64;
    const int bm = blockIdx.y * 128;
    const int bn = blockIdx.x * 128;

    const int lr = tid & 127;        // loader row
    const int lk = (tid >> 7) * 16;  // loader k offset (elements)

    const size_t xbase = (size_t)(bm + lr) * 1024 + lk;
    const size_t wbase = (size_t)(bn + lr) * 1024 + lk;

    float acc[2][8][4];
#pragma unroll
    for (int mt = 0; mt < 2; mt++)
#pragma unroll
        for (int nt = 0; nt < 8; nt++)
#pragma unroll
            for (int i = 0; i < 4; i++) acc[mt][nt][i] = 0.0f;

    const unsigned xa0 = sptr(&Xs[(m0 + (lane & 15)) * GST + (lane >> 4) * 8]);
    const unsigned xa1 = sptr(&Xs[(m0 + 16 + (lane & 15)) * GST + (lane >> 4) * 8]);
    const unsigned wb = sptr(&Ws[(n0 + 8 * (lane >> 4) + (lane & 7)) * GST + ((lane >> 3) & 1) * 8]);

    float4 xv[4], wv[4];
#pragma unroll
    for (int j = 0; j < 4; j++) {
        xv[j] = *(const float4*)&X[xbase + 4 * j];
        wv[j] = *(const float4*)&W[wbase + 4 * j];
    }

    for (int k0 = 0; k0 < 1024; k0 += 32) {
        __syncthreads();  // previous compute done reading smem
        {
            __half2 hx[8], hw[8];
#pragma unroll
            for (int j = 0; j < 4; j++) {
                hx[2 * j] = __floats2half2_rn(xv[j].x, xv[j].y);
                hx[2 * j + 1] = __floats2half2_rn(xv[j].z, xv[j].w);
                hw[2 * j] = __floats2half2_rn(wv[j].x, wv[j].y);
                hw[2 * j + 1] = __floats2half2_rn(wv[j].z, wv[j].w);
            }
            *(uint4*)&Xs[lr * GST + lk] = *(uint4*)&hx[0];
            *(uint4*)&Xs[lr * GST + lk + 8] = *(uint4*)&hx[4];
            *(uint4*)&Ws[lr * GST + lk] = *(uint4*)&hw[0];
            *(uint4*)&Ws[lr * GST + lk + 8] = *(uint4*)&hw[4];
        }
        __syncthreads();
        if (k0 + 32 < 1024) {
#pragma unroll
            for (int j = 0; j < 4; j++) {  // prefetch next tile; overlaps mma below
                xv[j] = *(const float4*)&X[xbase + k0 + 32 + 4 * j];
                wv[j] = *(const float4*)&W[wbase + k0 + 32 + 4 * j];
            }
        }

#pragma unroll
        for (int ks = 0; ks < 2; ks++) {
            unsigned a0[4], a1[4];
            ldsm4(a0[0], a0[1], a0[2], a0[3], xa0 + ks * 32);
            ldsm4(a1[0], a1[1], a1[2], a1[3], xa1 + ks * 32);
#pragma unroll
            for (int j = 0; j < 4; j++) {
                unsigned b[4];
                ldsm4(b[0], b[1], b[2], b[3], wb + j * 16 * GST * 2 + ks * 32);
                mma16(acc[0][2 * j], a0, b[0], b[1]);
                mma16(acc[0][2 * j + 1], a0, b[2], b[3]);
                mma16(acc[1][2 * j], a1, b[0], b[1]);
                mma16(acc[1][2 * j + 1], a1, b[2], b[3]);
            }
        }
    }

    // epilogue: bias + relu + fp16 store
#pragma unroll
    for (int nt = 0; nt < 8; nt++) {
        int n = bn + n0 + 8 * nt + 2 * tig;
        float b0 = __ldg(&bias[n]), b1 = __ldg(&bias[n + 1]);
#pragma unroll
        for (int mt = 0; mt < 2; mt++) {
            int m = bm + m0 + 16 * mt + g;
            float v0 = acc[mt][nt][0] + b0, v1 = acc[mt][nt][1] + b1;
            v0 = v0 > 0.f ? v0 : 0.f;
            v1 = v1 > 0.f ? v1 : 0.f;
            *(__half2*)&out[(size_t)m * 1024 + n] = __floats2half2_rn(v0, v1);
            float v2 = acc[mt][nt][2] + b0, v3 = acc[mt][nt][3] + b1;
            v2 = v2 > 0.f ? v2 : 0.f;
            v3 = v3 > 0.f ? v3 : 0.f;
            *(__half2*)&out[(size_t)(m + 8) * 1024 + n] = __floats2half2_rn(v2, v3);
        }
    }
}

// =====================================================================
// Flash attention: cp.async double-buffered K/V, P-frags in registers,
// one __syncthreads per key tile. + scrambled reshape + residual.
// =====================================================================
#define KST 72  // halves per smem row (144B = 36 banks: conflict-free LDSM)
#define OST 68  // floats per row of the final O overlay
#define STAGE_H (64 * KST)          // halves per K (or V) stage
#define ATTN_SMEM ((4 * STAGE_H + 128 * KST) * 2)  // KB[2] | VB[2] | Qs  (55296 B)

__global__ void __launch_bounds__(256) attn_mma(const int* __restrict__ amask,
                                                const float* __restrict__ queries,
                                                float* __restrict__ out) {
    extern __shared__ __align__(16) char smbase[];
    __half* KB = (__half*)smbase;                   // 2 stages of [64][KST]
    __half* VB = (__half*)smbase + 2 * STAGE_H;     // 2 stages of [64][KST]
    __half* Qs = (__half*)smbase + 4 * STAGE_H;     // [128][KST]
    float* So = (float*)smbase;                     // final O overlay (fits in KB+VB)

    const int tid = threadIdx.x;
    const int warp = tid >> 5, lane = tid & 31;
    const int g = lane >> 2, tig = lane & 3;
    const int b = blockIdx.z, h = blockIdx.y;
    const int q0 = blockIdx.x * 128;
    const int qw = warp * 16;

    // cp.async staging map: row = tid>>2 (0..63), col group = (tid&3)*16 halves
    const int crow = tid >> 2;
    const int ccol = (tid & 3) * 16;
    const unsigned kdst = sptr(&KB[crow * KST + ccol]);
    const unsigned vdst = sptr(&VB[crow * KST + ccol]);

    // ---- issue tile 0 loads first (overlap with Q staging below) ----
    {
        const size_t gofs = (size_t)(b * 2048 + crow) * 1024 + h * 64 + ccol;
        cpa16(kdst, g_K + gofs);
        cpa16(kdst + 16, g_K + gofs + 8);
        cpa16(vdst, g_V + gofs);
        cpa16(vdst + 16, g_V + gofs + 8);
        asm volatile("cp.async.commit_group;");
    }

    // ---- stage Q (scaled by 0.125) warp-locally, frags to registers ----
    {
        int row = tid >> 1;              // warp w stages exactly its own rows 16w..16w+15
        int koff = (tid & 1) * 32;
        const __half* qsrc = g_Q + (size_t)(b * 2048 + q0 + row) * 1024 + h * 64 + koff;
        const __half2 sc = __floats2half2_rn(0.125f, 0.125f);
        __half2 v[16];
        *(uint4*)&v[0] = *(const uint4*)&qsrc[0];
        *(uint4*)&v[4] = *(const uint4*)&qsrc[8];
        *(uint4*)&v[8] = *(const uint4*)&qsrc[16];
        *(uint4*)&v[12] = *(const uint4*)&qsrc[24];
#pragma unroll
        for (int j = 0; j < 16; j++) v[j] = __hmul2(v[j], sc);
        *(uint4*)&Qs[row * KST + koff] = *(uint4*)&v[0];
        *(uint4*)&Qs[row * KST + koff + 8] = *(uint4*)&v[4];
        *(uint4*)&Qs[row * KST + koff + 16] = *(uint4*)&v[8];
        *(uint4*)&Qs[row * KST + koff + 24] = *(uint4*)&v[12];
    }
    __syncwarp();
    unsigned qf[4][4];
    {
        unsigned qa = sptr(&Qs[(qw + (lane & 15)) * KST + (lane >> 4) * 8]);
#pragma unroll
        for (int ks = 0; ks < 4; ks++)
            ldsm4(qf[ks][0], qf[ks][1], qf[ks][2], qf[ks][3], qa + ks * 32);
    }
    const float fA = (amask[b * 2048 + q0 + qw + g] != 0) ? 1.0f : 0.0f;
    const float fB = (amask[b * 2048 + q0 + qw + g + 8] != 0) ? 1.0f : 0.0f;

    float mA = -1e30f, mB = -1e30f, lA = 0.0f, lB = 0.0f;
    float o[8][4];
#pragma unroll
    for (int nt = 0; nt < 8; nt++)
#pragma unroll
        for (int i = 0; i < 4; i++) o[nt][i] = 0.0f;

    // lane-dependent LDSM bases (stage 0); stage offset = STAGE_H*2 bytes
    const unsigned kb0 = sptr(&KB[(8 * (lane >> 4) + (lane & 7)) * KST + ((lane >> 3) & 1) * 8]);
    const unsigned vb0 = sptr(&VB[(8 * ((lane >> 3) & 1) + (lane & 7)) * KST + (lane >> 4) * 8]);

    for (int jt = 0; jt < 32; jt++) {
        const int st = jt & 1;
        asm volatile("cp.async.wait_group 0;" ::: "memory");
        __syncthreads();  // tile jt visible to all; all warps done reading stage st^1

        if (jt + 1 < 32) {  // issue tile jt+1 into the other stage; overlaps compute
            const size_t gofs = (size_t)(b * 2048 + (jt + 1) * 64 + crow) * 1024 + h * 64 + ccol;
            const unsigned soff = (st ^ 1) * (STAGE_H * 2);
            cpa16(kdst + soff, g_K + gofs);
            cpa16(kdst + soff + 16, g_K + gofs + 8);
            cpa16(vdst + soff, g_V + gofs);
            cpa16(vdst + soff + 16, g_V + gofs + 8);
            asm volatile("cp.async.commit_group;");
        }

        // ---- S = Q @ K^T (16q x 64k per warp) ----
        const unsigned kb = kb0 + st * (STAGE_H * 2);
        float s[8][4];
#pragma unroll
        for (int nt = 0; nt < 8; nt++)
#pragma unroll
            for (int i = 0; i < 4; i++) s[nt][i] = 0.0f;
#pragma unroll
        for (int ks = 0; ks < 4; ks++) {
#pragma unroll
            for (int j = 0; j < 4; j++) {
                unsigned bfr[4];
                ldsm4(bfr[0], bfr[1], bfr[2], bfr[3], kb + j * (16 * KST * 2) + ks * 32);
                mma16(s[2 * j], qf[ks], bfr[0], bfr[1]);
                mma16(s[2 * j + 1], qf[ks], bfr[2], bfr[3]);
            }
        }
#pragma unroll
        for (int nt = 0; nt < 8; nt++) {
            s[nt][0] *= fA; s[nt][1] *= fA;
            s[nt][2] *= fB; s[nt][3] *= fB;
        }

        // ---- online softmax in registers (quad shuffles) ----
        float mxA = s[0][0], mxB = s[0][2];
#pragma unroll
        for (int nt = 0; nt < 8; nt++) {
            mxA = fmaxf(mxA, fmaxf(s[nt][0], s[nt][1]));
            mxB = fmaxf(mxB, fmaxf(s[nt][2], s[nt][3]));
        }
        mxA = fmaxf(mxA, __shfl_xor_sync(0xffffffffu, mxA, 1));
        mxA = fmaxf(mxA, __shfl_xor_sync(0xffffffffu, mxA, 2));
        mxB = fmaxf(mxB, __shfl_xor_sync(0xffffffffu, mxB, 1));
        mxB = fmaxf(mxB, __shfl_xor_sync(0xffffffffu, mxB, 2));
        float mnA = fmaxf(mA, mxA), mnB = fmaxf(mB, mxB);
        float cA = __expf(mA - mnA), cB = __expf(mB - mnB);
        mA = mnA; mB = mnB;
        float sumA = 0.0f, sumB = 0.0f;
#pragma unroll
        for (int nt = 0; nt < 8; nt++) {
            s[nt][0] = __expf(s[nt][0] - mnA);
            s[nt][1] = __expf(s[nt][1] - mnA);
            s[nt][2] = __expf(s[nt][2] - mnB);
            s[nt][3] = __expf(s[nt][3] - mnB);
            sumA += s[nt][0] + s[nt][1];
            sumB += s[nt][2] + s[nt][3];
        }
        sumA += __shfl_xor_sync(0xffffffffu, sumA, 1);
        sumA += __shfl_xor_sync(0xffffffffu, sumA, 2);
        sumB += __shfl_xor_sync(0xffffffffu, sumB, 1);
        sumB += __shfl_xor_sync(0xffffffffu, sumB, 2);
        lA = lA * cA + sumA;
        lB = lB * cB + sumB;

        // ---- rescale O; P A-frags built directly from S accum registers ----
#pragma unroll
        for (int nt = 0; nt < 8; nt++) {
            o[nt][0] *= cA; o[nt][1] *= cA;
            o[nt][2] *= cB; o[nt][3] *= cB;
        }
        const unsigned vb = vb0 + st * (STAGE_H * 2);
#pragma unroll
        for (int ks = 0; ks < 4; ks++) {
            unsigned pa[4];
            pa[0] = h2u(s[2 * ks][0], s[2 * ks][1]);
            pa[1] = h2u(s[2 * ks][2], s[2 * ks][3]);
            pa[2] = h2u(s[2 * ks + 1][0], s[2 * ks + 1][1]);
            pa[3] = h2u(s[2 * ks + 1][2], s[2 * ks + 1][3]);
#pragma unroll
            for (int j = 0; j < 4; j++) {
                unsigned vfr[4];
                ldsm4t(vfr[0], vfr[1], vfr[2], vfr[3], vb + ks * (16 * KST * 2) + j * 32);
                mma16(o[2 * j], pa, vfr[0], vfr[1]);
                mma16(o[2 * j + 1], pa, vfr[2], vfr[3]);
            }
        }
    }

    __syncthreads();  // all compute done; overlay fp32 O on the K/V buffer region
    {
        float rA = 1.0f / lA, rB = 1.0f / lB;
#pragma unroll
        for (int nt = 0; nt < 8; nt++) {
            *(float2*)&So[(qw + g) * OST + 8 * nt + 2 * tig] =
                make_float2(o[nt][0] * rA, o[nt][1] * rA);
            *(float2*)&So[(qw + g + 8) * OST + 8 * nt + 2 * tig] =
                make_float2(o[nt][2] * rB, o[nt][3] * rB);
        }
    }
    __syncthreads();

    // ---- scrambled reshape + residual:
    //   out[b, 128h + 2d + e, q % 1024] = O[q][d] + queries[...], e = (q0 >= 1024)
    const int e = (q0 >= 1024) ? 1 : 0;
    const int dd = tid >> 2;
    const int qq = (tid & 3) * 16;
    const int srow = 128 * h + 2 * dd + e;
    const int col0 = q0 & 1023;
    const float* qp = queries + (size_t)(b * 2048 + srow) * 1024 + col0;
    float* op = out + (size_t)(b * 2048 + srow) * 1024 + col0;
#pragma unroll
    for (int half = 0; half < 128; half += 64) {
#pragma unroll
        for (int t = 0; t < 16; t += 4) {
            int ql = half + qq + t;
            float4 qv = *(const float4*)&qp[ql];
            float4 r;
            r.x = So[(ql + 0) * OST + dd] + qv.x;
            r.y = So[(ql + 1) * OST + dd] + qv.y;
            r.z = So[(ql + 2) * OST + dd] + qv.z;
            r.w = So[(ql + 3) * OST + dd] + qv.w;
            *(float4*)&op[ql] = r;
        }
    }
}

// ---------------- launch ----------------
extern "C" void kernel_launch(void* const* d_in, const int* in_sizes, int n_in, void* d_out,
                              int out_size) {
    const float* queries = (const float*)d_in[0];
    const float* keys = (const float*)d_in[1];
    const float* values = (const float*)d_in[2];
    const int* amask = (const int*)d_in[3];
    const float* Wq = (const float*)d_in[4];
    const float* bq = (const float*)d_in[5];
    const float* Wk = (const float*)d_in[6];
    const float* bk = (const float*)d_in[7];
    const float* Wv = (const float*)d_in[8];
    const float* bv = (const float*)d_in[9];
    float* out = (float*)d_out;

    dim3 g1(8, 32, 3);
    qkv_gemm<<<g1, 256>>>(queries, keys, values, Wq, Wk, Wv, bq, bk, bv);

    cudaFuncSetAttribute(attn_mma, cudaFuncAttributeMaxDynamicSharedMemorySize, ATTN_SMEM);
    dim3 g2(16, 16, 2);
    attn_mma<<<g2, 256, ATTN_SMEM>>>(amask, queries, out);
}

// round 6
// speedup vs baseline: 6.2152x; 1.4984x over previous
#include <cuda_runtime.h>
#include <cuda_fp16.h>

// Problem constants
#define BB 2
#define SS 2048
#define DD 1024

// fp16 staging buffers (device globals: no allocation allowed)
__device__ __half g_Q[BB * SS * DD];
__device__ __half g_K[BB * SS * DD];
__device__ __half g_V[BB * SS * DD];
__device__ __half g_Xh[3][BB * SS * DD];   // fp16 copies of queries/keys/values
__device__ __half g_Wh[3][DD * DD];        // fp16 copies of Wq/Wk/Wv

// ---------- helpers ----------
__device__ __forceinline__ unsigned sptr(const void* p) {
    return (unsigned)__cvta_generic_to_shared(p);
}
__device__ __forceinline__ void ldsm4(unsigned& r0, unsigned& r1, unsigned& r2, unsigned& r3,
                                      unsigned addr) {
    asm volatile("ldmatrix.sync.aligned.m8n8.x4.shared.b16 {%0,%1,%2,%3}, [%4];"
                 : "=r"(r0), "=r"(r1), "=r"(r2), "=r"(r3)
                 : "r"(addr));
}
__device__ __forceinline__ void ldsm4t(unsigned& r0, unsigned& r1, unsigned& r2, unsigned& r3,
                                       unsigned addr) {
    asm volatile("ldmatrix.sync.aligned.m8n8.x4.trans.shared.b16 {%0,%1,%2,%3}, [%4];"
                 : "=r"(r0), "=r"(r1), "=r"(r2), "=r"(r3)
                 : "r"(addr));
}
// D(16x8,f32) += A(16x16,f16) * B(16x8,f16)
__device__ __forceinline__ void mma16(float c[4], const unsigned a[4], unsigned b0, unsigned b1) {
    asm volatile(
        "mma.sync.aligned.m16n8k16.row.col.f32.f16.f16.f32 "
        "{%0,%1,%2,%3},{%4,%5,%6,%7},{%8,%9},{%0,%1,%2,%3};"
        : "+f"(c[0]), "+f"(c[1]), "+f"(c[2]), "+f"(c[3])
        : "r"(a[0]), "r"(a[1]), "r"(a[2]), "r"(a[3]), "r"(b0), "r"(b1));
}
__device__ __forceinline__ void cpa16(unsigned s, const void* g) {
    asm volatile("cp.async.cg.shared.global [%0], [%1], 16;" ::"r"(s), "l"(g));
}
__device__ __forceinline__ unsigned h2u(float a, float b) {
    __half2 h = __floats2half2_rn(a, b);
    return *(unsigned*)&h;
}

// =====================================================================
// fp32 -> fp16 conversion pass (bandwidth-bound, ~94MB traffic)
// =====================================================================
__global__ void __launch_bounds__(256) cvt_kernel(
    const float* __restrict__ q, const float* __restrict__ k, const float* __restrict__ v,
    const float* __restrict__ wq, const float* __restrict__ wk, const float* __restrict__ wv) {
    const int sel = blockIdx.y;
    const float* src;
    __half* dst;
    int n4;
    switch (sel) {
        case 0: src = q;  dst = g_Xh[0]; n4 = BB * SS * DD / 4; break;
        case 1: src = k;  dst = g_Xh[1]; n4 = BB * SS * DD / 4; break;
        case 2: src = v;  dst = g_Xh[2]; n4 = BB * SS * DD / 4; break;
        case 3: src = wq; dst = g_Wh[0]; n4 = DD * DD / 4; break;
        case 4: src = wk; dst = g_Wh[1]; n4 = DD * DD / 4; break;
        default: src = wv; dst = g_Wh[2]; n4 = DD * DD / 4; break;
    }
    const int stride = gridDim.x * blockDim.x;
    for (int i = blockIdx.x * blockDim.x + threadIdx.x; i < n4; i += stride) {
        float4 f = ((const float4*)src)[i];
        __half2 h0 = __floats2half2_rn(f.x, f.y);
        __half2 h1 = __floats2half2_rn(f.z, f.w);
        uint2 o;
        o.x = *(unsigned*)&h0;
        o.y = *(unsigned*)&h1;
        ((uint2*)dst)[i] = o;
    }
}

// =====================================================================
// QKV projection (fp16 in/out): out[m,n] = relu(sum_k X[m,k]*W[n,k] + b[n])
// M=4096, N=K=1024. 256 thr (8 warps 4x2), tile 128x128, kc=64.
// cp.async 2-stage double-buffered pipeline; ldmatrix + m16n8k16.
// =====================================================================
#define QST 72                   // halves per smem row (conflict-free LDSM)
#define QSTG (128 * QST)         // halves per X (or W) stage
#define GEMM_SMEM (4 * QSTG * 2) // bytes: XB[2] | WB[2] = 73728

__global__ void __launch_bounds__(256, 2) qkv_gemm(
    const float* __restrict__ bq, const float* __restrict__ bk, const float* __restrict__ bv) {
    const __half* X = g_Xh[blockIdx.z];
    const __half* W = g_Wh[blockIdx.z];
    const float* bias = (blockIdx.z == 0) ? bq : (blockIdx.z == 1) ? bk : bv;
    __half* out = (blockIdx.z == 0) ? g_Q : (blockIdx.z == 1) ? g_K : g_V;

    extern __shared__ __align__(16) char smraw[];
    __half* XB = (__half*)smraw;             // 2 stages [128][QST]
    __half* WB = (__half*)smraw + 2 * QSTG;  // 2 stages [128][QST]

    const int tid = threadIdx.x;
    const int warp = tid >> 5, lane = tid & 31;
    const int g = lane >> 2, tig = lane & 3;
    const int m0 = (warp >> 1) * 32;
    const int n0 = (warp & 1) * 64;
    const int bm = blockIdx.y * 128;
    const int bn = blockIdx.x * 128;

    // cp.async map: 2 threads per row; each thread covers halves [ccol, ccol+32)
    const int crow = tid >> 1;       // 0..127
    const int ccol = (tid & 1) * 32; // 0 or 32 halves
    const unsigned xdst = sptr(&XB[crow * QST + ccol]);
    const unsigned wdst = sptr(&WB[crow * QST + ccol]);
    const size_t xrow = (size_t)(bm + crow) * 1024 + ccol;
    const size_t wrow = (size_t)(bn + crow) * 1024 + ccol;

    float acc[2][8][4];
#pragma unroll
    for (int mt = 0; mt < 2; mt++)
#pragma unroll
        for (int nt = 0; nt < 8; nt++)
#pragma unroll
            for (int i = 0; i < 4; i++) acc[mt][nt][i] = 0.0f;

    const unsigned xa0 = sptr(&XB[(m0 + (lane & 15)) * QST + (lane >> 4) * 8]);
    const unsigned xa1 = sptr(&XB[(m0 + 16 + (lane & 15)) * QST + (lane >> 4) * 8]);
    const unsigned wbb = sptr(&WB[(n0 + 8 * (lane >> 4) + (lane & 7)) * QST + ((lane >> 3) & 1) * 8]);

    // issue k-tile 0
    {
#pragma unroll
        for (int c = 0; c < 4; c++) {
            cpa16(xdst + c * 16, X + xrow + c * 8);
            cpa16(wdst + c * 16, W + wrow + c * 8);
        }
        asm volatile("cp.async.commit_group;");
    }

    for (int it = 0; it < 16; it++) {
        const int st = it & 1;
        asm volatile("cp.async.wait_group 0;" ::: "memory");
        __syncthreads();  // tile it visible; stage st^1 free of readers

        if (it + 1 < 16) {  // issue tile it+1 into the other stage (overlaps mma)
            const int k0 = (it + 1) * 64;
            const unsigned soff = (st ^ 1) * (QSTG * 2);
#pragma unroll
            for (int c = 0; c < 4; c++) {
                cpa16(xdst + soff + c * 16, X + xrow + k0 + c * 8);
                cpa16(wdst + soff + c * 16, W + wrow + k0 + c * 8);
            }
            asm volatile("cp.async.commit_group;");
        }

        const unsigned sa = st * (QSTG * 2);
#pragma unroll
        for (int ks = 0; ks < 4; ks++) {
            unsigned a0[4], a1[4];
            ldsm4(a0[0], a0[1], a0[2], a0[3], xa0 + sa + ks * 32);
            ldsm4(a1[0], a1[1], a1[2], a1[3], xa1 + sa + ks * 32);
#pragma unroll
            for (int j = 0; j < 4; j++) {
                unsigned b[4];
                ldsm4(b[0], b[1], b[2], b[3], wbb + sa + j * (16 * QST * 2) + ks * 32);
                mma16(acc[0][2 * j], a0, b[0], b[1]);
                mma16(acc[0][2 * j + 1], a0, b[2], b[3]);
                mma16(acc[1][2 * j], a1, b[0], b[1]);
                mma16(acc[1][2 * j + 1], a1, b[2], b[3]);
            }
        }
    }

    // epilogue: bias + relu + fp16 store
#pragma unroll
    for (int nt = 0; nt < 8; nt++) {
        int n = bn + n0 + 8 * nt + 2 * tig;
        float b0 = __ldg(&bias[n]), b1 = __ldg(&bias[n + 1]);
#pragma unroll
        for (int mt = 0; mt < 2; mt++) {
            int m = bm + m0 + 16 * mt + g;
            float v0 = acc[mt][nt][0] + b0, v1 = acc[mt][nt][1] + b1;
            v0 = v0 > 0.f ? v0 : 0.f;
            v1 = v1 > 0.f ? v1 : 0.f;
            *(__half2*)&out[(size_t)m * 1024 + n] = __floats2half2_rn(v0, v1);
            float v2 = acc[mt][nt][2] + b0, v3 = acc[mt][nt][3] + b1;
            v2 = v2 > 0.f ? v2 : 0.f;
            v3 = v3 > 0.f ? v3 : 0.f;
            *(__half2*)&out[(size_t)(m + 8) * 1024 + n] = __floats2half2_rn(v2, v3);
        }
    }
}

// =====================================================================
// Flash attention: cp.async double-buffered K/V, P-frags in registers,
// one __syncthreads per key tile. + scrambled reshape + residual.
// =====================================================================
#define KST 72  // halves per smem row (conflict-free LDSM)
#define OST 68  // floats per row of the final O overlay
#define STAGE_H (64 * KST)
#define ATTN_SMEM ((4 * STAGE_H + 128 * KST) * 2)  // KB[2] | VB[2] | Qs (55296 B)

__global__ void __launch_bounds__(256) attn_mma(const int* __restrict__ amask,
                                                const float* __restrict__ queries,
                                                float* __restrict__ out) {
    extern __shared__ __align__(16) char smbase[];
    __half* KB = (__half*)smbase;
    __half* VB = (__half*)smbase + 2 * STAGE_H;
    __half* Qs = (__half*)smbase + 4 * STAGE_H;
    float* So = (float*)smbase;

    const int tid = threadIdx.x;
    const int warp = tid >> 5, lane = tid & 31;
    const int g = lane >> 2, tig = lane & 3;
    const int b = blockIdx.z, h = blockIdx.y;
    const int q0 = blockIdx.x * 128;
    const int qw = warp * 16;

    const int crow = tid >> 2;
    const int ccol = (tid & 3) * 16;
    const unsigned kdst = sptr(&KB[crow * KST + ccol]);
    const unsigned vdst = sptr(&VB[crow * KST + ccol]);

    {
        const size_t gofs = (size_t)(b * 2048 + crow) * 1024 + h * 64 + ccol;
        cpa16(kdst, g_K + gofs);
        cpa16(kdst + 16, g_K + gofs + 8);
        cpa16(vdst, g_V + gofs);
        cpa16(vdst + 16, g_V + gofs + 8);
        asm volatile("cp.async.commit_group;");
    }

    // ---- stage Q (scaled by 0.125) warp-locally, frags to registers ----
    {
        int row = tid >> 1;
        int koff = (tid & 1) * 32;
        const __half* qsrc = g_Q + (size_t)(b * 2048 + q0 + row) * 1024 + h * 64 + koff;
        const __half2 sc = __floats2half2_rn(0.125f, 0.125f);
        __half2 v[16];
        *(uint4*)&v[0] = *(const uint4*)&qsrc[0];
        *(uint4*)&v[4] = *(const uint4*)&qsrc[8];
        *(uint4*)&v[8] = *(const uint4*)&qsrc[16];
        *(uint4*)&v[12] = *(const uint4*)&qsrc[24];
#pragma unroll
        for (int j = 0; j < 16; j++) v[j] = __hmul2(v[j], sc);
        *(uint4*)&Qs[row * KST + koff] = *(uint4*)&v[0];
        *(uint4*)&Qs[row * KST + koff + 8] = *(uint4*)&v[4];
        *(uint4*)&Qs[row * KST + koff + 16] = *(uint4*)&v[8];
        *(uint4*)&Qs[row * KST + koff + 24] = *(uint4*)&v[12];
    }
    __syncwarp();
    unsigned qf[4][4];
    {
        unsigned qa = sptr(&Qs[(qw + (lane & 15)) * KST + (lane >> 4) * 8]);
#pragma unroll
        for (int ks = 0; ks < 4; ks++)
            ldsm4(qf[ks][0], qf[ks][1], qf[ks][2], qf[ks][3], qa + ks * 32);
    }
    const float fA = (amask[b * 2048 + q0 + qw + g] != 0) ? 1.0f : 0.0f;
    const float fB = (amask[b * 2048 + q0 + qw + g + 8] != 0) ? 1.0f : 0.0f;

    float mA = -1e30f, mB = -1e30f, lA = 0.0f, lB = 0.0f;
    float o[8][4];
#pragma unroll
    for (int nt = 0; nt < 8; nt++)
#pragma unroll
        for (int i = 0; i < 4; i++) o[nt][i] = 0.0f;

    const unsigned kb0 = sptr(&KB[(8 * (lane >> 4) + (lane & 7)) * KST + ((lane >> 3) & 1) * 8]);
    const unsigned vb0 = sptr(&VB[(8 * ((lane >> 3) & 1) + (lane & 7)) * KST + (lane >> 4) * 8]);

    for (int jt = 0; jt < 32; jt++) {
        const int st = jt & 1;
        asm volatile("cp.async.wait_group 0;" ::: "memory");
        __syncthreads();

        if (jt + 1 < 32) {
            const size_t gofs = (size_t)(b * 2048 + (jt + 1) * 64 + crow) * 1024 + h * 64 + ccol;
            const unsigned soff = (st ^ 1) * (STAGE_H * 2);
            cpa16(kdst + soff, g_K + gofs);
            cpa16(kdst + soff + 16, g_K + gofs + 8);
            cpa16(vdst + soff, g_V + gofs);
            cpa16(vdst + soff + 16, g_V + gofs + 8);
            asm volatile("cp.async.commit_group;");
        }

        // ---- S = Q @ K^T ----
        const unsigned kb = kb0 + st * (STAGE_H * 2);
        float s[8][4];
#pragma unroll
        for (int nt = 0; nt < 8; nt++)
#pragma unroll
            for (int i = 0; i < 4; i++) s[nt][i] = 0.0f;
#pragma unroll
        for (int ks = 0; ks < 4; ks++) {
#pragma unroll
            for (int j = 0; j < 4; j++) {
                unsigned bfr[4];
                ldsm4(bfr[0], bfr[1], bfr[2], bfr[3], kb + j * (16 * KST * 2) + ks * 32);
                mma16(s[2 * j], qf[ks], bfr[0], bfr[1]);
                mma16(s[2 * j + 1], qf[ks], bfr[2], bfr[3]);
            }
        }
#pragma unroll
        for (int nt = 0; nt < 8; nt++) {
            s[nt][0] *= fA; s[nt][1] *= fA;
            s[nt][2] *= fB; s[nt][3] *= fB;
        }

        // ---- online softmax in registers ----
        float mxA = s[0][0], mxB = s[0][2];
#pragma unroll
        for (int nt = 0; nt < 8; nt++) {
            mxA = fmaxf(mxA, fmaxf(s[nt][0], s[nt][1]));
            mxB = fmaxf(mxB, fmaxf(s[nt][2], s[nt][3]));
        }
        mxA = fmaxf(mxA, __shfl_xor_sync(0xffffffffu, mxA, 1));
        mxA = fmaxf(mxA, __shfl_xor_sync(0xffffffffu, mxA, 2));
        mxB = fmaxf(mxB, __shfl_xor_sync(0xffffffffu, mxB, 1));
        mxB = fmaxf(mxB, __shfl_xor_sync(0xffffffffu, mxB, 2));
        float mnA = fmaxf(mA, mxA), mnB = fmaxf(mB, mxB);
        float cA = __expf(mA - mnA), cB = __expf(mB - mnB);
        mA = mnA; mB = mnB;
        float sumA = 0.0f, sumB = 0.0f;
#pragma unroll
        for (int nt = 0; nt < 8; nt++) {
            s[nt][0] = __expf(s[nt][0] - mnA);
            s[nt][1] = __expf(s[nt][1] - mnA);
            s[nt][2] = __expf(s[nt][2] - mnB);
            s[nt][3] = __expf(s[nt][3] - mnB);
            sumA += s[nt][0] + s[nt][1];
            sumB += s[nt][2] + s[nt][3];
        }
        sumA += __shfl_xor_sync(0xffffffffu, sumA, 1);
        sumA += __shfl_xor_sync(0xffffffffu, sumA, 2);
        sumB += __shfl_xor_sync(0xffffffffu, sumB, 1);
        sumB += __shfl_xor_sync(0xffffffffu, sumB, 2);
        lA = lA * cA + sumA;
        lB = lB * cB + sumB;

        // ---- rescale O; P A-frags built directly from S accum registers ----
#pragma unroll
        for (int nt = 0; nt < 8; nt++) {
            o[nt][0] *= cA; o[nt][1] *= cA;
            o[nt][2] *= cB; o[nt][3] *= cB;
        }
        const unsigned vb = vb0 + st * (STAGE_H * 2);
#pragma unroll
        for (int ks = 0; ks < 4; ks++) {
            unsigned pa[4];
            pa[0] = h2u(s[2 * ks][0], s[2 * ks][1]);
            pa[1] = h2u(s[2 * ks][2], s[2 * ks][3]);
            pa[2] = h2u(s[2 * ks + 1][0], s[2 * ks + 1][1]);
            pa[3] = h2u(s[2 * ks + 1][2], s[2 * ks + 1][3]);
#pragma unroll
            for (int j = 0; j < 4; j++) {
                unsigned vfr[4];
                ldsm4t(vfr[0], vfr[1], vfr[2], vfr[3], vb + ks * (16 * KST * 2) + j * 32);
                mma16(o[2 * j], pa, vfr[0], vfr[1]);
                mma16(o[2 * j + 1], pa, vfr[2], vfr[3]);
            }
        }
    }

    __syncthreads();
    {
        float rA = 1.0f / lA, rB = 1.0f / lB;
#pragma unroll
        for (int nt = 0; nt < 8; nt++) {
            *(float2*)&So[(qw + g) * OST + 8 * nt + 2 * tig] =
                make_float2(o[nt][0] * rA, o[nt][1] * rA);
            *(float2*)&So[(qw + g + 8) * OST + 8 * nt + 2 * tig] =
                make_float2(o[nt][2] * rB, o[nt][3] * rB);
        }
    }
    __syncthreads();

    // ---- scrambled reshape + residual ----
    const int e = (q0 >= 1024) ? 1 : 0;
    const int dd = tid >> 2;
    const int qq = (tid & 3) * 16;
    const int srow = 128 * h + 2 * dd + e;
    const int col0 = q0 & 1023;
    const float* qp = queries + (size_t)(b * 2048 + srow) * 1024 + col0;
    float* op = out + (size_t)(b * 2048 + srow) * 1024 + col0;
#pragma unroll
    for (int half = 0; half < 128; half += 64) {
#pragma unroll
        for (int t = 0; t < 16; t += 4) {
            int ql = half + qq + t;
            float4 qv = *(const float4*)&qp[ql];
            float4 r;
            r.x = So[(ql + 0) * OST + dd] + qv.x;
            r.y = So[(ql + 1) * OST + dd] + qv.y;
            r.z = So[(ql + 2) * OST + dd] + qv.z;
            r.w = So[(ql + 3) * OST + dd] + qv.w;
            *(float4*)&op[ql] = r;
        }
    }
}

// ---------------- launch ----------------
extern "C" void kernel_launch(void* const* d_in, const int* in_sizes, int n_in, void* d_out,
                              int out_size) {
    const float* queries = (const float*)d_in[0];
    const float* keys = (const float*)d_in[1];
    const float* values = (const float*)d_in[2];
    const int* amask = (const int*)d_in[3];
    const float* Wq = (const float*)d_in[4];
    const float* bq = (const float*)d_in[5];
    const float* Wk = (const float*)d_in[6];
    const float* bk = (const float*)d_in[7];
    const float* Wv = (const float*)d_in[8];
    const float* bv = (const float*)d_in[9];
    float* out = (float*)d_out;

    dim3 gc(512, 6, 1);
    cvt_kernel<<<gc, 256>>>(queries, keys, values, Wq, Wk, Wv);

    cudaFuncSetAttribute(qkv_gemm, cudaFuncAttributeMaxDynamicSharedMemorySize, GEMM_SMEM);
    dim3 g1(8, 32, 3);
    qkv_gemm<<<g1, 256, GEMM_SMEM>>>(bq, bk, bv);

    cudaFuncSetAttribute(attn_mma, cudaFuncAttributeMaxDynamicSharedMemorySize, ATTN_SMEM);
    dim3 g2(16, 16, 2);
    attn_mma<<<g2, 256, ATTN_SMEM>>>(amask, queries, out);
}

// round 7
// speedup vs baseline: 6.4758x; 1.0419x over previous
#include <cuda_runtime.h>
#include <cuda_fp16.h>

// Problem constants
#define BB 2
#define SS 2048
#define DD 1024

// fp16 staging buffers (device globals: no allocation allowed)
__device__ __half g_Q[BB * SS * DD];
__device__ __half g_K[BB * SS * DD];
__device__ __half g_V[BB * SS * DD];
__device__ __half g_Xh[3][BB * SS * DD];   // fp16 copies of queries/keys/values
__device__ __half g_Wh[3][DD * DD];        // fp16 copies of Wq/Wk/Wv

// ---------- helpers ----------
__device__ __forceinline__ unsigned sptr(const void* p) {
    return (unsigned)__cvta_generic_to_shared(p);
}
__device__ __forceinline__ void ldsm4(unsigned& r0, unsigned& r1, unsigned& r2, unsigned& r3,
                                      unsigned addr) {
    asm volatile("ldmatrix.sync.aligned.m8n8.x4.shared.b16 {%0,%1,%2,%3}, [%4];"
                 : "=r"(r0), "=r"(r1), "=r"(r2), "=r"(r3)
                 : "r"(addr));
}
__device__ __forceinline__ void ldsm4t(unsigned& r0, unsigned& r1, unsigned& r2, unsigned& r3,
                                       unsigned addr) {
    asm volatile("ldmatrix.sync.aligned.m8n8.x4.trans.shared.b16 {%0,%1,%2,%3}, [%4];"
                 : "=r"(r0), "=r"(r1), "=r"(r2), "=r"(r3)
                 : "r"(addr));
}
// D(16x8,f32) += A(16x16,f16) * B(16x8,f16)
__device__ __forceinline__ void mma16(float c[4], const unsigned a[4], unsigned b0, unsigned b1) {
    asm volatile(
        "mma.sync.aligned.m16n8k16.row.col.f32.f16.f16.f32 "
        "{%0,%1,%2,%3},{%4,%5,%6,%7},{%8,%9},{%0,%1,%2,%3};"
        : "+f"(c[0]), "+f"(c[1]), "+f"(c[2]), "+f"(c[3])
        : "r"(a[0]), "r"(a[1]), "r"(a[2]), "r"(a[3]), "r"(b0), "r"(b1));
}
__device__ __forceinline__ void cpa16(unsigned s, const void* g) {
    asm volatile("cp.async.cg.shared.global [%0], [%1], 16;" ::"r"(s), "l"(g));
}
__device__ __forceinline__ unsigned h2u(float a, float b) {
    __half2 h = __floats2half2_rn(a, b);
    return *(unsigned*)&h;
}
__device__ __forceinline__ float ex2(float x) {
    float y;
    asm("ex2.approx.ftz.f32 %0, %1;" : "=f"(y) : "f"(x));
    return y;
}

// =====================================================================
// fp32 -> fp16 conversion pass (bandwidth-bound, ~94MB traffic)
// =====================================================================
__global__ void __launch_bounds__(256) cvt_kernel(
    const float* __restrict__ q, const float* __restrict__ k, const float* __restrict__ v,
    const float* __restrict__ wq, const float* __restrict__ wk, const float* __restrict__ wv) {
    const int sel = blockIdx.y;
    const float* src;
    __half* dst;
    int n4;
    switch (sel) {
        case 0: src = q;  dst = g_Xh[0]; n4 = BB * SS * DD / 4; break;
        case 1: src = k;  dst = g_Xh[1]; n4 = BB * SS * DD / 4; break;
        case 2: src = v;  dst = g_Xh[2]; n4 = BB * SS * DD / 4; break;
        case 3: src = wq; dst = g_Wh[0]; n4 = DD * DD / 4; break;
        case 4: src = wk; dst = g_Wh[1]; n4 = DD * DD / 4; break;
        default: src = wv; dst = g_Wh[2]; n4 = DD * DD / 4; break;
    }
    const int stride = gridDim.x * blockDim.x;
    for (int i = blockIdx.x * blockDim.x + threadIdx.x; i < n4; i += stride) {
        float4 f = ((const float4*)src)[i];
        __half2 h0 = __floats2half2_rn(f.x, f.y);
        __half2 h1 = __floats2half2_rn(f.z, f.w);
        uint2 o;
        o.x = *(unsigned*)&h0;
        o.y = *(unsigned*)&h1;
        ((uint2*)dst)[i] = o;
    }
}

// =====================================================================
// QKV projection (fp16 in/out): out[m,n] = relu(sum_k X[m,k]*W[n,k] + b[n])
// M=4096, N=K=1024. 256 thr (8 warps 4x2), tile 128x128, kc=64.
// 3-stage cp.async pipeline, wait_group 1 (prefetch distance 2).
// =====================================================================
#define QST 72                   // halves per smem row (conflict-free LDSM)
#define QSTG (128 * QST)         // halves per X (or W) stage
#define GEMM_SMEM (6 * QSTG * 2) // bytes: XB[3] | WB[3] = 110592

__global__ void __launch_bounds__(256, 2) qkv_gemm(
    const float* __restrict__ bq, const float* __restrict__ bk, const float* __restrict__ bv) {
    const __half* X = g_Xh[blockIdx.z];
    const __half* W = g_Wh[blockIdx.z];
    const float* bias = (blockIdx.z == 0) ? bq : (blockIdx.z == 1) ? bk : bv;
    __half* out = (blockIdx.z == 0) ? g_Q : (blockIdx.z == 1) ? g_K : g_V;

    extern __shared__ __align__(16) char smraw[];
    __half* XB = (__half*)smraw;             // 3 stages [128][QST]
    __half* WB = (__half*)smraw + 3 * QSTG;  // 3 stages [128][QST]

    const int tid = threadIdx.x;
    const int warp = tid >> 5, lane = tid & 31;
    const int g = lane >> 2, tig = lane & 3;
    const int m0 = (warp >> 1) * 32;
    const int n0 = (warp & 1) * 64;
    const int bm = blockIdx.y * 128;
    const int bn = blockIdx.x * 128;

    // cp.async map: 2 threads per row; each thread covers halves [ccol, ccol+32)
    const int crow = tid >> 1;       // 0..127
    const int ccol = (tid & 1) * 32; // 0 or 32 halves
    const unsigned xdst = sptr(&XB[crow * QST + ccol]);
    const unsigned wdst = sptr(&WB[crow * QST + ccol]);
    const size_t xrow = (size_t)(bm + crow) * 1024 + ccol;
    const size_t wrow = (size_t)(bn + crow) * 1024 + ccol;

    float acc[2][8][4];
#pragma unroll
    for (int mt = 0; mt < 2; mt++)
#pragma unroll
        for (int nt = 0; nt < 8; nt++)
#pragma unroll
            for (int i = 0; i < 4; i++) acc[mt][nt][i] = 0.0f;

    const unsigned xa0 = sptr(&XB[(m0 + (lane & 15)) * QST + (lane >> 4) * 8]);
    const unsigned xa1 = sptr(&XB[(m0 + 16 + (lane & 15)) * QST + (lane >> 4) * 8]);
    const unsigned wbb = sptr(&WB[(n0 + 8 * (lane >> 4) + (lane & 7)) * QST + ((lane >> 3) & 1) * 8]);

    // prologue: issue k-tiles 0 and 1 into stages 0, 1
#pragma unroll
    for (int p = 0; p < 2; p++) {
        const unsigned soff = p * (QSTG * 2);
        const int k0 = p * 64;
#pragma unroll
        for (int c = 0; c < 4; c++) {
            cpa16(xdst + soff + c * 16, X + xrow + k0 + c * 8);
            cpa16(wdst + soff + c * 16, W + wrow + k0 + c * 8);
        }
        asm volatile("cp.async.commit_group;");
    }

    int st = 0, st2 = 2;  // compute stage, prefetch stage
    for (int it = 0; it < 16; it++) {
        asm volatile("cp.async.wait_group 1;" ::: "memory");
        __syncthreads();  // tile it visible everywhere; stage st2 (tile it-1) free

        if (it + 2 < 16) {  // issue tile it+2 into stage st2 (overlaps mma)
            const int k0 = (it + 2) * 64;
            const unsigned soff = st2 * (QSTG * 2);
#pragma unroll
            for (int c = 0; c < 4; c++) {
                cpa16(xdst + soff + c * 16, X + xrow + k0 + c * 8);
                cpa16(wdst + soff + c * 16, W + wrow + k0 + c * 8);
            }
        }
        asm volatile("cp.async.commit_group;");  // always commit (empty in tail)

        const unsigned sa = st * (QSTG * 2);
#pragma unroll
        for (int ks = 0; ks < 4; ks++) {
            unsigned a0[4], a1[4];
            ldsm4(a0[0], a0[1], a0[2], a0[3], xa0 + sa + ks * 32);
            ldsm4(a1[0], a1[1], a1[2], a1[3], xa1 + sa + ks * 32);
#pragma unroll
            for (int j = 0; j < 4; j++) {
                unsigned b[4];
                ldsm4(b[0], b[1], b[2], b[3], wbb + sa + j * (16 * QST * 2) + ks * 32);
                mma16(acc[0][2 * j], a0, b[0], b[1]);
                mma16(acc[0][2 * j + 1], a0, b[2], b[3]);
                mma16(acc[1][2 * j], a1, b[0], b[1]);
                mma16(acc[1][2 * j + 1], a1, b[2], b[3]);
            }
        }
        st = (st == 2) ? 0 : st + 1;
        st2 = (st2 == 2) ? 0 : st2 + 1;
    }

    // epilogue: bias + relu + fp16 store
#pragma unroll
    for (int nt = 0; nt < 8; nt++) {
        int n = bn + n0 + 8 * nt + 2 * tig;
        float b0 = __ldg(&bias[n]), b1 = __ldg(&bias[n + 1]);
#pragma unroll
        for (int mt = 0; mt < 2; mt++) {
            int m = bm + m0 + 16 * mt + g;
            float v0 = acc[mt][nt][0] + b0, v1 = acc[mt][nt][1] + b1;
            v0 = v0 > 0.f ? v0 : 0.f;
            v1 = v1 > 0.f ? v1 : 0.f;
            *(__half2*)&out[(size_t)m * 1024 + n] = __floats2half2_rn(v0, v1);
            float v2 = acc[mt][nt][2] + b0, v3 = acc[mt][nt][3] + b1;
            v2 = v2 > 0.f ? v2 : 0.f;
            v3 = v3 > 0.f ? v3 : 0.f;
            *(__half2*)&out[(size_t)(m + 8) * 1024 + n] = __floats2half2_rn(v2, v3);
        }
    }
}

// =====================================================================
// Flash attention: 3-stage cp.async K/V, P-frags in registers, base-2
// softmax (log2e folded into Q scale). + scrambled reshape + residual.
// =====================================================================
#define KST 72  // halves per smem row (conflict-free LDSM)
#define OST 68  // floats per row of the final O overlay
#define STAGE_H (64 * KST)                          // halves per tensor-stage
#define ATTN_SMEM ((6 * STAGE_H + 128 * KST) * 2)   // KB[3] | VB[3] | Qs (73728 B)

__global__ void __launch_bounds__(256) attn_mma(const int* __restrict__ amask,
                                                const float* __restrict__ queries,
                                                float* __restrict__ out) {
    extern __shared__ __align__(16) char smbase[];
    __half* KB = (__half*)smbase;                   // 3 stages [64][KST]
    __half* VB = (__half*)smbase + 3 * STAGE_H;     // 3 stages [64][KST]
    __half* Qs = (__half*)smbase + 6 * STAGE_H;     // [128][KST]
    float* So = (float*)smbase;                     // final O overlay

    const int tid = threadIdx.x;
    const int warp = tid >> 5, lane = tid & 31;
    const int g = lane >> 2, tig = lane & 3;
    const int b = blockIdx.z, h = blockIdx.y;
    const int q0 = blockIdx.x * 128;
    const int qw = warp * 16;

    const int crow = tid >> 2;
    const int ccol = (tid & 3) * 16;
    const unsigned kdst = sptr(&KB[crow * KST + ccol]);
    const unsigned vdst = sptr(&VB[crow * KST + ccol]);

    // prologue: issue key-tiles 0 and 1 into stages 0, 1
#pragma unroll
    for (int p = 0; p < 2; p++) {
        const size_t gofs = (size_t)(b * 2048 + p * 64 + crow) * 1024 + h * 64 + ccol;
        const unsigned soff = p * (STAGE_H * 2);
        cpa16(kdst + soff, g_K + gofs);
        cpa16(kdst + soff + 16, g_K + gofs + 8);
        cpa16(vdst + soff, g_V + gofs);
        cpa16(vdst + soff + 16, g_V + gofs + 8);
        asm volatile("cp.async.commit_group;");
    }

    // ---- stage Q scaled by 0.125*log2(e) (base-2 softmax), frags to regs ----
    {
        int row = tid >> 1;
        int koff = (tid & 1) * 32;
        const __half* qsrc = g_Q + (size_t)(b * 2048 + q0 + row) * 1024 + h * 64 + koff;
        const float qs = 0.125f * 1.4426950408889634f;
        const __half2 sc = __floats2half2_rn(qs, qs);
        __half2 v[16];
        *(uint4*)&v[0] = *(const uint4*)&qsrc[0];
        *(uint4*)&v[4] = *(const uint4*)&qsrc[8];
        *(uint4*)&v[8] = *(const uint4*)&qsrc[16];
        *(uint4*)&v[12] = *(const uint4*)&qsrc[24];
#pragma unroll
        for (int j = 0; j < 16; j++) v[j] = __hmul2(v[j], sc);
        *(uint4*)&Qs[row * KST + koff] = *(uint4*)&v[0];
        *(uint4*)&Qs[row * KST + koff + 8] = *(uint4*)&v[4];
        *(uint4*)&Qs[row * KST + koff + 16] = *(uint4*)&v[8];
        *(uint4*)&Qs[row * KST + koff + 24] = *(uint4*)&v[12];
    }
    __syncwarp();
    unsigned qf[4][4];
    {
        unsigned qa = sptr(&Qs[(qw + (lane & 15)) * KST + (lane >> 4) * 8]);
#pragma unroll
        for (int ks = 0; ks < 4; ks++)
            ldsm4(qf[ks][0], qf[ks][1], qf[ks][2], qf[ks][3], qa + ks * 32);
    }
    const float fA = (amask[b * 2048 + q0 + qw + g] != 0) ? 1.0f : 0.0f;
    const float fB = (amask[b * 2048 + q0 + qw + g + 8] != 0) ? 1.0f : 0.0f;

    float mA = -1e30f, mB = -1e30f, lA = 0.0f, lB = 0.0f;
    float o[8][4];
#pragma unroll
    for (int nt = 0; nt < 8; nt++)
#pragma unroll
        for (int i = 0; i < 4; i++) o[nt][i] = 0.0f;

    const unsigned kb0 = sptr(&KB[(8 * (lane >> 4) + (lane & 7)) * KST + ((lane >> 3) & 1) * 8]);
    const unsigned vb0 = sptr(&VB[(8 * ((lane >> 3) & 1) + (lane & 7)) * KST + (lane >> 4) * 8]);

    int st = 0, st2 = 2;
    for (int jt = 0; jt < 32; jt++) {
        asm volatile("cp.async.wait_group 1;" ::: "memory");
        __syncthreads();  // tile jt visible; stage st2 free of readers

        if (jt + 2 < 32) {  // issue tile jt+2 into stage st2
            const size_t gofs = (size_t)(b * 2048 + (jt + 2) * 64 + crow) * 1024 + h * 64 + ccol;
            const unsigned soff = st2 * (STAGE_H * 2);
            cpa16(kdst + soff, g_K + gofs);
            cpa16(kdst + soff + 16, g_K + gofs + 8);
            cpa16(vdst + soff, g_V + gofs);
            cpa16(vdst + soff + 16, g_V + gofs + 8);
        }
        asm volatile("cp.async.commit_group;");  // always commit (empty in tail)

        // ---- S = Q @ K^T (logits already in log2 domain) ----
        const unsigned kb = kb0 + st * (STAGE_H * 2);
        float s[8][4];
#pragma unroll
        for (int nt = 0; nt < 8; nt++)
#pragma unroll
            for (int i = 0; i < 4; i++) s[nt][i] = 0.0f;
#pragma unroll
        for (int ks = 0; ks < 4; ks++) {
#pragma unroll
            for (int j = 0; j < 4; j++) {
                unsigned bfr[4];
                ldsm4(bfr[0], bfr[1], bfr[2], bfr[3], kb + j * (16 * KST * 2) + ks * 32);
                mma16(s[2 * j], qf[ks], bfr[0], bfr[1]);
                mma16(s[2 * j + 1], qf[ks], bfr[2], bfr[3]);
            }
        }
#pragma unroll
        for (int nt = 0; nt < 8; nt++) {
            s[nt][0] *= fA; s[nt][1] *= fA;
            s[nt][2] *= fB; s[nt][3] *= fB;
        }

        // ---- online softmax in registers, base 2 ----
        float mxA = s[0][0], mxB = s[0][2];
#pragma unroll
        for (int nt = 0; nt < 8; nt++) {
            mxA = fmaxf(mxA, fmaxf(s[nt][0], s[nt][1]));
            mxB = fmaxf(mxB, fmaxf(s[nt][2], s[nt][3]));
        }
        mxA = fmaxf(mxA, __shfl_xor_sync(0xffffffffu, mxA, 1));
        mxA = fmaxf(mxA, __shfl_xor_sync(0xffffffffu, mxA, 2));
        mxB = fmaxf(mxB, __shfl_xor_sync(0xffffffffu, mxB, 1));
        mxB = fmaxf(mxB, __shfl_xor_sync(0xffffffffu, mxB, 2));
        float mnA = fmaxf(mA, mxA), mnB = fmaxf(mB, mxB);
        float cA = ex2(mA - mnA), cB = ex2(mB - mnB);
        mA = mnA; mB = mnB;
        float sumA = 0.0f, sumB = 0.0f;
#pragma unroll
        for (int nt = 0; nt < 8; nt++) {
            s[nt][0] = ex2(s[nt][0] - mnA);
            s[nt][1] = ex2(s[nt][1] - mnA);
            s[nt][2] = ex2(s[nt][2] - mnB);
            s[nt][3] = ex2(s[nt][3] - mnB);
            sumA += s[nt][0] + s[nt][1];
            sumB += s[nt][2] + s[nt][3];
        }
        sumA += __shfl_xor_sync(0xffffffffu, sumA, 1);
        sumA += __shfl_xor_sync(0xffffffffu, sumA, 2);
        sumB += __shfl_xor_sync(0xffffffffu, sumB, 1);
        sumB += __shfl_xor_sync(0xffffffffu, sumB, 2);
        lA = lA * cA + sumA;
        lB = lB * cB + sumB;

        // ---- rescale O; P A-frags built directly from S accum registers ----
#pragma unroll
        for (int nt = 0; nt < 8; nt++) {
            o[nt][0] *= cA; o[nt][1] *= cA;
            o[nt][2] *= cB; o[nt][3] *= cB;
        }
        const unsigned vb = vb0 + st * (STAGE_H * 2);
#pragma unroll
        for (int ks = 0; ks < 4; ks++) {
            unsigned pa[4];
            pa[0] = h2u(s[2 * ks][0], s[2 * ks][1]);
            pa[1] = h2u(s[2 * ks][2], s[2 * ks][3]);
            pa[2] = h2u(s[2 * ks + 1][0], s[2 * ks + 1][1]);
            pa[3] = h2u(s[2 * ks + 1][2], s[2 * ks + 1][3]);
#pragma unroll
            for (int j = 0; j < 4; j++) {
                unsigned vfr[4];
                ldsm4t(vfr[0], vfr[1], vfr[2], vfr[3], vb + ks * (16 * KST * 2) + j * 32);
                mma16(o[2 * j], pa, vfr[0], vfr[1]);
                mma16(o[2 * j + 1], pa, vfr[2], vfr[3]);
            }
        }
        st = (st == 2) ? 0 : st + 1;
        st2 = (st2 == 2) ? 0 : st2 + 1;
    }

    __syncthreads();
    {
        float rA = 1.0f / lA, rB = 1.0f / lB;
#pragma unroll
        for (int nt = 0; nt < 8; nt++) {
            *(float2*)&So[(qw + g) * OST + 8 * nt + 2 * tig] =
                make_float2(o[nt][0] * rA, o[nt][1] * rA);
            *(float2*)&So[(qw + g + 8) * OST + 8 * nt + 2 * tig] =
                make_float2(o[nt][2] * rB, o[nt][3] * rB);
        }
    }
    __syncthreads();

    // ---- scrambled reshape + residual ----
    const int e = (q0 >= 1024) ? 1 : 0;
    const int dd = tid >> 2;
    const int qq = (tid & 3) * 16;
    const int srow = 128 * h + 2 * dd + e;
    const int col0 = q0 & 1023;
    const float* qp = queries + (size_t)(b * 2048 + srow) * 1024 + col0;
    float* op = out + (size_t)(b * 2048 + srow) * 1024 + col0;
#pragma unroll
    for (int half = 0; half < 128; half += 64) {
#pragma unroll
        for (int t = 0; t < 16; t += 4) {
            int ql = half + qq + t;
            float4 qv = *(const float4*)&qp[ql];
            float4 r;
            r.x = So[(ql + 0) * OST + dd] + qv.x;
            r.y = So[(ql + 1) * OST + dd] + qv.y;
            r.z = So[(ql + 2) * OST + dd] + qv.z;
            r.w = So[(ql + 3) * OST + dd] + qv.w;
            *(float4*)&op[ql] = r;
        }
    }
}

// ---------------- launch ----------------
extern "C" void kernel_launch(void* const* d_in, const int* in_sizes, int n_in, void* d_out,
                              int out_size) {
    const float* queries = (const float*)d_in[0];
    const float* keys = (const float*)d_in[1];
    const float* values = (const float*)d_in[2];
    const int* amask = (const int*)d_in[3];
    const float* Wq = (const float*)d_in[4];
    const float* bq = (const float*)d_in[5];
    const float* Wk = (const float*)d_in[6];
    const float* bk = (const float*)d_in[7];
    const float* Wv = (const float*)d_in[8];
    const float* bv = (const float*)d_in[9];
    float* out = (float*)d_out;

    dim3 gc(512, 6, 1);
    cvt_kernel<<<gc, 256>>>(queries, keys, values, Wq, Wk, Wv);

    cudaFuncSetAttribute(qkv_gemm, cudaFuncAttributeMaxDynamicSharedMemorySize, GEMM_SMEM);
    dim3 g1(8, 32, 3);
    qkv_gemm<<<g1, 256, GEMM_SMEM>>>(bq, bk, bv);

    cudaFuncSetAttribute(attn_mma, cudaFuncAttributeMaxDynamicSharedMemorySize, ATTN_SMEM);
    dim3 g2(16, 16, 2);
    attn_mma<<<g2, 256, ATTN_SMEM>>>(amask, queries, out);
}